// round 3
// baseline (speedup 1.0000x reference)
#include <cuda_runtime.h>

#define NTOK 4096
#define CDIM 256
#define HEADS 8
#define DHEAD 32
#define MASK_NEGF (-9.0e15f)

// scratch (allocation-free rule: device globals)
__device__ float g_qkv[NTOK * 3 * CDIM];   // [N, 3*C]  (q|k|v per token)
__device__ float g_att[NTOK * CDIM];       // attention output [N, C]

__device__ __forceinline__ float ex2(float x) {
    float y;
    asm("ex2.approx.ftz.f32 %0, %1;" : "=f"(y) : "f"(x));
    return y;
}

// ---------------------------------------------------------------------------
// GEMM: Y[m][n] = sum_k A[m][k] * B[n][k]  (+ bias[n])   A:[M,K] B:[Nn,K]
// 64x64 tile, 256 threads, 4x4 microtile, K-step 16, k-major smem.
// Register double-buffer: next K-step's LDG issued right after the sync,
// landing while the current step computes.
// ---------------------------------------------------------------------------
__global__ __launch_bounds__(256) void gemm_nt(
    const float* __restrict__ A, const float* __restrict__ B,
    const float* __restrict__ bias, float* __restrict__ Y,
    int M, int Nn, int K)
{
    __shared__ float As[16][68];
    __shared__ float Bs[16][68];

    const int tid = threadIdx.x;
    const int tx = tid & 15;
    const int ty = tid >> 4;
    const int m0 = blockIdx.y << 6;
    const int n0 = blockIdx.x << 6;

    const int lr = tid >> 2;          // 0..63
    const int lk = (tid & 3) << 2;    // 0,4,8,12

    const float* Ap = A + (size_t)(m0 + lr) * K + lk;
    const float* Bp = B + (size_t)(n0 + lr) * K + lk;

    float c[4][4];
#pragma unroll
    for (int i = 0; i < 4; i++)
#pragma unroll
        for (int j = 0; j < 4; j++) c[i][j] = 0.0f;

    float4 av = *(const float4*)(Ap);
    float4 bv = *(const float4*)(Bp);

    for (int k0 = 0; k0 < K; k0 += 16) {
        __syncthreads();
        As[lk + 0][lr] = av.x; As[lk + 1][lr] = av.y;
        As[lk + 2][lr] = av.z; As[lk + 3][lr] = av.w;
        Bs[lk + 0][lr] = bv.x; Bs[lk + 1][lr] = bv.y;
        Bs[lk + 2][lr] = bv.z; Bs[lk + 3][lr] = bv.w;
        __syncthreads();
        if (k0 + 16 < K) {
            av = *(const float4*)(Ap + k0 + 16);
            bv = *(const float4*)(Bp + k0 + 16);
        }
#pragma unroll
        for (int kk = 0; kk < 16; kk++) {
            float4 a = *(const float4*)&As[kk][ty << 2];
            float4 b = *(const float4*)&Bs[kk][tx << 2];
            c[0][0] += a.x * b.x; c[0][1] += a.x * b.y; c[0][2] += a.x * b.z; c[0][3] += a.x * b.w;
            c[1][0] += a.y * b.x; c[1][1] += a.y * b.y; c[1][2] += a.y * b.z; c[1][3] += a.y * b.w;
            c[2][0] += a.z * b.x; c[2][1] += a.z * b.y; c[2][2] += a.z * b.z; c[2][3] += a.z * b.w;
            c[3][0] += a.w * b.x; c[3][1] += a.w * b.y; c[3][2] += a.w * b.z; c[3][3] += a.w * b.w;
        }
    }

    float b0 = 0.f, b1 = 0.f, b2 = 0.f, b3 = 0.f;
    if (bias) {
        const int nb = n0 + (tx << 2);
        b0 = bias[nb + 0]; b1 = bias[nb + 1]; b2 = bias[nb + 2]; b3 = bias[nb + 3];
    }
#pragma unroll
    for (int i = 0; i < 4; i++) {
        const int mrow = m0 + (ty << 2) + i;
        float4 o;
        o.x = c[i][0] + b0; o.y = c[i][1] + b1;
        o.z = c[i][2] + b2; o.w = c[i][3] + b3;
        *(float4*)(Y + (size_t)mrow * Nn + n0 + (tx << 2)) = o;
    }
}

// ---------------------------------------------------------------------------
// Flash attention, fp32. Block = 64 query rows x 1 head, 128 threads.
// Thread pair (tid, tid^1) shares one query row; half=tid&1 owns 32 of the
// 64 keys of each tile; partials combined at the end via shfl.
// __launch_bounds__(128,3): 168-reg budget -> no local spills of s[]/qreg.
// K/V tiles register-double-buffered: tile t+1's LDGs issue right after the
// post-STS sync and land during tile t's ~4000-cycle compute.
// Softmax in base-2 (q pre-scaled by 1/sqrt(32)*log2(e)); exp = MUFU.EX2.
// ---------------------------------------------------------------------------
__global__ __launch_bounds__(128, 3) void attn_kernel(
    const float* __restrict__ qkv, const int* __restrict__ adj,
    float* __restrict__ out)
{
    __shared__ float Ks[64][36];  // stride 36 to spread banks
    __shared__ float Vs[64][36];

    const int tid = threadIdx.x;
    const int ql = tid >> 1;
    const int half = tid & 1;
    const int qg = (blockIdx.x << 6) + ql;
    const int h = blockIdx.y;
    const float qscale = 0.17677669529663687f * 1.4426950408889634f;

    // query row -> registers (both pair threads hold full row), pre-scaled
    float qreg[DHEAD];
    {
        const float4* qp4 = (const float4*)(qkv + (size_t)qg * 768 + h * DHEAD);
#pragma unroll
        for (int i = 0; i < 8; i++) {
            float4 t = qp4[i];
            qreg[4 * i + 0] = t.x * qscale; qreg[4 * i + 1] = t.y * qscale;
            qreg[4 * i + 2] = t.z * qscale; qreg[4 * i + 3] = t.w * qscale;
        }
    }

    float m = MASK_NEGF;
    float l = 0.0f;
    float acc[DHEAD];
#pragma unroll
    for (int d = 0; d < DHEAD; d++) acc[d] = 0.0f;

    const int lr = tid >> 1;          // tile row this thread loads
    const int lc = (tid & 1) * 16;    // 16-float chunk
    const int kbase = half * 32;      // this thread's key subset within tile

    const float* kvbase = qkv + (size_t)lr * 768 + CDIM + h * DHEAD + lc;
    const int* arow = adj + (size_t)qg * NTOK + kbase;

    // prefetch tile 0 into registers
    float4 kr0, kr1, kr2, kr3, vr0, vr1, vr2, vr3;
    {
        const float4* kp4 = (const float4*)(kvbase);
        const float4* vp4 = (const float4*)(kvbase + CDIM);
        kr0 = kp4[0]; kr1 = kp4[1]; kr2 = kp4[2]; kr3 = kp4[3];
        vr0 = vp4[0]; vr1 = vp4[1]; vr2 = vp4[2]; vr3 = vp4[3];
    }

    for (int kt = 0; kt < NTOK; kt += 64) {
        __syncthreads();   // previous tile's readers done
        *(float4*)&Ks[lr][lc + 0]  = kr0;
        *(float4*)&Ks[lr][lc + 4]  = kr1;
        *(float4*)&Ks[lr][lc + 8]  = kr2;
        *(float4*)&Ks[lr][lc + 12] = kr3;
        *(float4*)&Vs[lr][lc + 0]  = vr0;
        *(float4*)&Vs[lr][lc + 4]  = vr1;
        *(float4*)&Vs[lr][lc + 8]  = vr2;
        *(float4*)&Vs[lr][lc + 12] = vr3;
        __syncthreads();

        // issue next tile's global loads (land during this tile's compute)
        if (kt + 64 < NTOK) {
            const float4* kp4 = (const float4*)(kvbase + (size_t)(kt + 64) * 768);
            const float4* vp4 = (const float4*)(kvbase + (size_t)(kt + 64) * 768 + CDIM);
            kr0 = kp4[0]; kr1 = kp4[1]; kr2 = kp4[2]; kr3 = kp4[3];
            vr0 = vp4[0]; vr1 = vp4[1]; vr2 = vp4[2]; vr3 = vp4[3];
        }

        // adj row loads issued before the S loop (front-batched, land during S)
        int4 a4r[8];
        {
            const int4* ap4 = (const int4*)(arow + kt);
#pragma unroll
            for (int k4 = 0; k4 < 8; k4++) a4r[k4] = ap4[k4];
        }

        // S = q . K^T for this thread's 32 keys (log2-domain)
        float s[32];
#pragma unroll
        for (int k = 0; k < 32; k++) s[k] = 0.0f;
#pragma unroll
        for (int d4 = 0; d4 < 8; d4++) {
            const float qx = qreg[4 * d4 + 0], qy = qreg[4 * d4 + 1];
            const float qz = qreg[4 * d4 + 2], qw = qreg[4 * d4 + 3];
#pragma unroll
            for (int k = 0; k < 32; k++) {
                float4 kv = *(const float4*)&Ks[kbase + k][4 * d4];
                s[k] += qx * kv.x + qy * kv.y + qz * kv.z + qw * kv.w;
            }
        }

        // mask
#pragma unroll
        for (int k4 = 0; k4 < 8; k4++) {
            if (a4r[k4].x <= 0) s[4 * k4 + 0] = MASK_NEGF;
            if (a4r[k4].y <= 0) s[4 * k4 + 1] = MASK_NEGF;
            if (a4r[k4].z <= 0) s[4 * k4 + 2] = MASK_NEGF;
            if (a4r[k4].w <= 0) s[4 * k4 + 3] = MASK_NEGF;
        }

        // online softmax in base-2 (pair-combined via shfl with lane tid^1)
        float mloc = s[0];
#pragma unroll
        for (int k = 1; k < 32; k++) mloc = fmaxf(mloc, s[k]);
        mloc = fmaxf(mloc, __shfl_xor_sync(0xffffffffu, mloc, 1));
        const float mnew = fmaxf(m, mloc);
        const float corr = ex2(m - mnew);
        m = mnew;

        float ls = 0.0f;
#pragma unroll
        for (int k = 0; k < 32; k++) {
            float p = ex2(s[k] - mnew);
            s[k] = p;
            ls += p;
        }
        ls += __shfl_xor_sync(0xffffffffu, ls, 1);
        l = l * corr + ls;

#pragma unroll
        for (int d = 0; d < DHEAD; d++) acc[d] *= corr;

        // acc += P . V  (this thread's keys, all 32 dh)
#pragma unroll
        for (int k = 0; k < 32; k++) {
            const float p = s[k];
#pragma unroll
            for (int d4 = 0; d4 < 8; d4++) {
                float4 vv = *(const float4*)&Vs[kbase + k][4 * d4];
                acc[4 * d4 + 0] += p * vv.x;
                acc[4 * d4 + 1] += p * vv.y;
                acc[4 * d4 + 2] += p * vv.z;
                acc[4 * d4 + 3] += p * vv.w;
            }
        }
    }

    // combine pair partials, normalize, store
    const float inv = 1.0f / l;
#pragma unroll
    for (int d = 0; d < DHEAD; d++) {
        float t = acc[d] + __shfl_xor_sync(0xffffffffu, acc[d], 1);
        acc[d] = t * inv;
    }
    float* op = out + (size_t)qg * CDIM + h * DHEAD;
    if (half == 0) {
#pragma unroll
        for (int j = 0; j < 4; j++) {
            float4 o; o.x = acc[4 * j]; o.y = acc[4 * j + 1];
            o.z = acc[4 * j + 2]; o.w = acc[4 * j + 3];
            *(float4*)(op + 4 * j) = o;
        }
    } else {
#pragma unroll
        for (int j = 4; j < 8; j++) {
            float4 o; o.x = acc[4 * j]; o.y = acc[4 * j + 1];
            o.z = acc[4 * j + 2]; o.w = acc[4 * j + 3];
            *(float4*)(op + 4 * j) = o;
        }
    }
}

// ---------------------------------------------------------------------------
extern "C" void kernel_launch(void* const* d_in, const int* in_sizes, int n_in,
                              void* d_out, int out_size)
{
    const float* x      = (const float*)d_in[0];
    const int*   adj    = (const int*)d_in[1];
    const float* w_qkv  = (const float*)d_in[2];
    const float* w_proj = (const float*)d_in[3];
    const float* b_proj = (const float*)d_in[4];
    float*       out    = (float*)d_out;

    void *p1 = nullptr, *p2 = nullptr;
    cudaGetSymbolAddress(&p1, g_qkv);
    cudaGetSymbolAddress(&p2, g_att);
    float* qkv = (float*)p1;
    float* att = (float*)p2;

    // 1) QKV projection: [4096, 768] = x [4096,256] @ w_qkv^T [256,768]
    {
        dim3 grid(768 / 64, NTOK / 64);
        gemm_nt<<<grid, 256>>>(x, w_qkv, nullptr, qkv, NTOK, 3 * CDIM, CDIM);
    }
    // 2) masked flash attention per head
    {
        dim3 grid(NTOK / 64, HEADS);
        attn_kernel<<<grid, 128>>>(qkv, adj, att);
    }
    // 3) output projection + bias
    {
        dim3 grid(CDIM / 64, NTOK / 64);
        gemm_nt<<<grid, 256>>>(att, w_proj, b_proj, out, NTOK, CDIM, CDIM);
    }
}

// round 4
// speedup vs baseline: 1.0238x; 1.0238x over previous
#include <cuda_runtime.h>

#define NTOK 4096
#define CDIM 256
#define HEADS 8
#define DHEAD 32
#define MASK_NEGF (-9.0e15f)

// scratch (allocation-free rule: device globals)
__device__ float g_qkv[NTOK * 3 * CDIM];   // [N, 3*C]  (q|k|v per token)
__device__ float g_att[NTOK * CDIM];       // attention output [N, C]

__device__ __forceinline__ float ex2(float x) {
    float y;
    asm("ex2.approx.ftz.f32 %0, %1;" : "=f"(y) : "f"(x));
    return y;
}

// ---------------------------------------------------------------------------
// GEMM: Y[m][n] = sum_k A[m][k] * B[n][k]  (+ bias[n])   A:[M,K] B:[Nn,K]
// 64x64 tile, 256 threads, 4x4 microtile, K-step 16, k-major smem.
// Register double-buffer: next K-step's LDG issued right after the sync.
// ---------------------------------------------------------------------------
__global__ __launch_bounds__(256) void gemm_nt(
    const float* __restrict__ A, const float* __restrict__ B,
    const float* __restrict__ bias, float* __restrict__ Y,
    int M, int Nn, int K)
{
    __shared__ float As[16][68];
    __shared__ float Bs[16][68];

    const int tid = threadIdx.x;
    const int tx = tid & 15;
    const int ty = tid >> 4;
    const int m0 = blockIdx.y << 6;
    const int n0 = blockIdx.x << 6;

    const int lr = tid >> 2;          // 0..63
    const int lk = (tid & 3) << 2;    // 0,4,8,12

    const float* Ap = A + (size_t)(m0 + lr) * K + lk;
    const float* Bp = B + (size_t)(n0 + lr) * K + lk;

    float c[4][4];
#pragma unroll
    for (int i = 0; i < 4; i++)
#pragma unroll
        for (int j = 0; j < 4; j++) c[i][j] = 0.0f;

    float4 av = *(const float4*)(Ap);
    float4 bv = *(const float4*)(Bp);

    for (int k0 = 0; k0 < K; k0 += 16) {
        __syncthreads();
        As[lk + 0][lr] = av.x; As[lk + 1][lr] = av.y;
        As[lk + 2][lr] = av.z; As[lk + 3][lr] = av.w;
        Bs[lk + 0][lr] = bv.x; Bs[lk + 1][lr] = bv.y;
        Bs[lk + 2][lr] = bv.z; Bs[lk + 3][lr] = bv.w;
        __syncthreads();
        if (k0 + 16 < K) {
            av = *(const float4*)(Ap + k0 + 16);
            bv = *(const float4*)(Bp + k0 + 16);
        }
#pragma unroll
        for (int kk = 0; kk < 16; kk++) {
            float4 a = *(const float4*)&As[kk][ty << 2];
            float4 b = *(const float4*)&Bs[kk][tx << 2];
            c[0][0] = fmaf(a.x, b.x, c[0][0]); c[0][1] = fmaf(a.x, b.y, c[0][1]);
            c[0][2] = fmaf(a.x, b.z, c[0][2]); c[0][3] = fmaf(a.x, b.w, c[0][3]);
            c[1][0] = fmaf(a.y, b.x, c[1][0]); c[1][1] = fmaf(a.y, b.y, c[1][1]);
            c[1][2] = fmaf(a.y, b.z, c[1][2]); c[1][3] = fmaf(a.y, b.w, c[1][3]);
            c[2][0] = fmaf(a.z, b.x, c[2][0]); c[2][1] = fmaf(a.z, b.y, c[2][1]);
            c[2][2] = fmaf(a.z, b.z, c[2][2]); c[2][3] = fmaf(a.z, b.w, c[2][3]);
            c[3][0] = fmaf(a.w, b.x, c[3][0]); c[3][1] = fmaf(a.w, b.y, c[3][1]);
            c[3][2] = fmaf(a.w, b.z, c[3][2]); c[3][3] = fmaf(a.w, b.w, c[3][3]);
        }
    }

    float b0 = 0.f, b1 = 0.f, b2 = 0.f, b3 = 0.f;
    if (bias) {
        const int nb = n0 + (tx << 2);
        b0 = bias[nb + 0]; b1 = bias[nb + 1]; b2 = bias[nb + 2]; b3 = bias[nb + 3];
    }
#pragma unroll
    for (int i = 0; i < 4; i++) {
        const int mrow = m0 + (ty << 2) + i;
        float4 o;
        o.x = c[i][0] + b0; o.y = c[i][1] + b1;
        o.z = c[i][2] + b2; o.w = c[i][3] + b3;
        *(float4*)(Y + (size_t)mrow * Nn + n0 + (tx << 2)) = o;
    }
}

// ---------------------------------------------------------------------------
// Flash attention, fp32. Block = 64 query rows x 1 head, 128 threads.
// Thread pair (tid, tid^1) shares one query row; half=tid&1 owns 32 of the
// 64 keys of each tile; partials combined at the end via shfl.
// __launch_bounds__(128,2): 255-reg budget. Peak live state
// (qreg32 + acc32 + s32 + K/V prefetch 32 + adj 32 + temps ~ 190) fits with
// NO local spills; 2 warps/SMSP saturate the FFMA pipe (rt=2, 32 indep chains).
// Explicit fmaf chains -> 4 FFMA per float4, no mul/add trees.
// Softmax in base-2 (q pre-scaled by 1/sqrt(32)*log2(e)); exp = MUFU.EX2.
// ---------------------------------------------------------------------------
__global__ __launch_bounds__(128, 2) void attn_kernel(
    const float* __restrict__ qkv, const int* __restrict__ adj,
    float* __restrict__ out)
{
    __shared__ float Ks[64][36];  // stride 36 to spread banks
    __shared__ float Vs[64][36];

    const int tid = threadIdx.x;
    const int ql = tid >> 1;
    const int half = tid & 1;
    const int qg = (blockIdx.x << 6) + ql;
    const int h = blockIdx.y;
    const float qscale = 0.17677669529663687f * 1.4426950408889634f;

    // query row -> registers (both pair threads hold full row), pre-scaled
    float qreg[DHEAD];
    {
        const float4* qp4 = (const float4*)(qkv + (size_t)qg * 768 + h * DHEAD);
#pragma unroll
        for (int i = 0; i < 8; i++) {
            float4 t = qp4[i];
            qreg[4 * i + 0] = t.x * qscale; qreg[4 * i + 1] = t.y * qscale;
            qreg[4 * i + 2] = t.z * qscale; qreg[4 * i + 3] = t.w * qscale;
        }
    }

    float m = MASK_NEGF;
    float l = 0.0f;
    float acc[DHEAD];
#pragma unroll
    for (int d = 0; d < DHEAD; d++) acc[d] = 0.0f;

    const int lr = tid >> 1;          // tile row this thread loads
    const int lc = (tid & 1) * 16;    // 16-float chunk
    const int kbase = half * 32;      // this thread's key subset within tile

    const float* kvbase = qkv + (size_t)lr * 768 + CDIM + h * DHEAD + lc;
    const int* arow = adj + (size_t)qg * NTOK + kbase;

    // prefetch tile 0 into registers
    float4 kr0, kr1, kr2, kr3, vr0, vr1, vr2, vr3;
    {
        const float4* kp4 = (const float4*)(kvbase);
        const float4* vp4 = (const float4*)(kvbase + CDIM);
        kr0 = kp4[0]; kr1 = kp4[1]; kr2 = kp4[2]; kr3 = kp4[3];
        vr0 = vp4[0]; vr1 = vp4[1]; vr2 = vp4[2]; vr3 = vp4[3];
    }

    for (int kt = 0; kt < NTOK; kt += 64) {
        __syncthreads();   // previous tile's readers done
        *(float4*)&Ks[lr][lc + 0]  = kr0;
        *(float4*)&Ks[lr][lc + 4]  = kr1;
        *(float4*)&Ks[lr][lc + 8]  = kr2;
        *(float4*)&Ks[lr][lc + 12] = kr3;
        *(float4*)&Vs[lr][lc + 0]  = vr0;
        *(float4*)&Vs[lr][lc + 4]  = vr1;
        *(float4*)&Vs[lr][lc + 8]  = vr2;
        *(float4*)&Vs[lr][lc + 12] = vr3;
        __syncthreads();

        // issue next tile's global loads (land during this tile's compute)
        if (kt + 64 < NTOK) {
            const float4* kp4 = (const float4*)(kvbase + (size_t)(kt + 64) * 768);
            const float4* vp4 = (const float4*)(kvbase + (size_t)(kt + 64) * 768 + CDIM);
            kr0 = kp4[0]; kr1 = kp4[1]; kr2 = kp4[2]; kr3 = kp4[3];
            vr0 = vp4[0]; vr1 = vp4[1]; vr2 = vp4[2]; vr3 = vp4[3];
        }

        // adj row loads issued before the S loop (front-batched, land during S)
        int4 a4r[8];
        {
            const int4* ap4 = (const int4*)(arow + kt);
#pragma unroll
            for (int k4 = 0; k4 < 8; k4++) a4r[k4] = ap4[k4];
        }

        // S = q . K^T for this thread's 32 keys (log2-domain), pure FFMA chains
        float s[32];
#pragma unroll
        for (int k = 0; k < 32; k++) s[k] = 0.0f;
#pragma unroll
        for (int d4 = 0; d4 < 8; d4++) {
            const float qx = qreg[4 * d4 + 0], qy = qreg[4 * d4 + 1];
            const float qz = qreg[4 * d4 + 2], qw = qreg[4 * d4 + 3];
#pragma unroll
            for (int k = 0; k < 32; k++) {
                float4 kv = *(const float4*)&Ks[kbase + k][4 * d4];
                float t = s[k];
                t = fmaf(qx, kv.x, t);
                t = fmaf(qy, kv.y, t);
                t = fmaf(qz, kv.z, t);
                t = fmaf(qw, kv.w, t);
                s[k] = t;
            }
        }

        // mask
#pragma unroll
        for (int k4 = 0; k4 < 8; k4++) {
            if (a4r[k4].x <= 0) s[4 * k4 + 0] = MASK_NEGF;
            if (a4r[k4].y <= 0) s[4 * k4 + 1] = MASK_NEGF;
            if (a4r[k4].z <= 0) s[4 * k4 + 2] = MASK_NEGF;
            if (a4r[k4].w <= 0) s[4 * k4 + 3] = MASK_NEGF;
        }

        // online softmax in base-2 (pair-combined via shfl with lane tid^1)
        float mloc = s[0];
#pragma unroll
        for (int k = 1; k < 32; k++) mloc = fmaxf(mloc, s[k]);
        mloc = fmaxf(mloc, __shfl_xor_sync(0xffffffffu, mloc, 1));
        const float mnew = fmaxf(m, mloc);
        const float corr = ex2(m - mnew);
        m = mnew;

        float ls = 0.0f;
#pragma unroll
        for (int k = 0; k < 32; k++) {
            float p = ex2(s[k] - mnew);
            s[k] = p;
            ls += p;
        }
        ls += __shfl_xor_sync(0xffffffffu, ls, 1);
        l = fmaf(l, corr, ls);

#pragma unroll
        for (int d = 0; d < DHEAD; d++) acc[d] *= corr;

        // acc += P . V  (this thread's keys, all 32 dh), pure FFMA
#pragma unroll
        for (int k = 0; k < 32; k++) {
            const float p = s[k];
#pragma unroll
            for (int d4 = 0; d4 < 8; d4++) {
                float4 vv = *(const float4*)&Vs[kbase + k][4 * d4];
                acc[4 * d4 + 0] = fmaf(p, vv.x, acc[4 * d4 + 0]);
                acc[4 * d4 + 1] = fmaf(p, vv.y, acc[4 * d4 + 1]);
                acc[4 * d4 + 2] = fmaf(p, vv.z, acc[4 * d4 + 2]);
                acc[4 * d4 + 3] = fmaf(p, vv.w, acc[4 * d4 + 3]);
            }
        }
    }

    // combine pair partials, normalize, store
    const float inv = 1.0f / l;
#pragma unroll
    for (int d = 0; d < DHEAD; d++) {
        float t = acc[d] + __shfl_xor_sync(0xffffffffu, acc[d], 1);
        acc[d] = t * inv;
    }
    float* op = out + (size_t)qg * CDIM + h * DHEAD;
    if (half == 0) {
#pragma unroll
        for (int j = 0; j < 4; j++) {
            float4 o; o.x = acc[4 * j]; o.y = acc[4 * j + 1];
            o.z = acc[4 * j + 2]; o.w = acc[4 * j + 3];
            *(float4*)(op + 4 * j) = o;
        }
    } else {
#pragma unroll
        for (int j = 4; j < 8; j++) {
            float4 o; o.x = acc[4 * j]; o.y = acc[4 * j + 1];
            o.z = acc[4 * j + 2]; o.w = acc[4 * j + 3];
            *(float4*)(op + 4 * j) = o;
        }
    }
}

// ---------------------------------------------------------------------------
extern "C" void kernel_launch(void* const* d_in, const int* in_sizes, int n_in,
                              void* d_out, int out_size)
{
    const float* x      = (const float*)d_in[0];
    const int*   adj    = (const int*)d_in[1];
    const float* w_qkv  = (const float*)d_in[2];
    const float* w_proj = (const float*)d_in[3];
    const float* b_proj = (const float*)d_in[4];
    float*       out    = (float*)d_out;

    void *p1 = nullptr, *p2 = nullptr;
    cudaGetSymbolAddress(&p1, g_qkv);
    cudaGetSymbolAddress(&p2, g_att);
    float* qkv = (float*)p1;
    float* att = (float*)p2;

    // 1) QKV projection: [4096, 768] = x [4096,256] @ w_qkv^T [256,768]
    {
        dim3 grid(768 / 64, NTOK / 64);
        gemm_nt<<<grid, 256>>>(x, w_qkv, nullptr, qkv, NTOK, 3 * CDIM, CDIM);
    }
    // 2) masked flash attention per head
    {
        dim3 grid(NTOK / 64, HEADS);
        attn_kernel<<<grid, 128>>>(qkv, adj, att);
    }
    // 3) output projection + bias
    {
        dim3 grid(CDIM / 64, NTOK / 64);
        gemm_nt<<<grid, 256>>>(att, w_proj, b_proj, out, NTOK, CDIM, CDIM);
    }
}

// round 5
// speedup vs baseline: 3.6268x; 3.5424x over previous
#include <cuda_runtime.h>
#include <cuda_bf16.h>
#include <cstdint>

#define NTOK 4096
#define CDIM 256
#define HEADS 8
#define NEGBIG (-1.0e30f)
#define MINIT  (-1.0e4f)   // softmax max floor; any true score is >> this

// scratch (allocation-free rule: device globals)
__device__ float    g_qkv[NTOK * 3 * CDIM];       // [N, 3*C] (q|k|v)
__device__ float    g_att[NTOK * CDIM];           // attention output [N, C]
__device__ uint32_t g_mask[NTOK * (NTOK / 32)];   // packed adj bitmask, 2 MB

__device__ __forceinline__ float ex2(float x) {
    float y;
    asm("ex2.approx.ftz.f32 %0, %1;" : "=f"(y) : "f"(x));
    return y;
}

// pack two floats -> bf16x2 (x in low half, y in high half)
__device__ __forceinline__ uint32_t pk(float x, float y) {
    uint32_t r;
    asm("cvt.rn.bf16x2.f32 %0, %1, %2;" : "=r"(r) : "f"(y), "f"(x));
    return r;
}

// split (x,y) into hi bf16x2 and lo bf16x2 residuals
__device__ __forceinline__ void split2(float x, float y, uint32_t& hi, uint32_t& lo) {
    uint32_t h = pk(x, y);
    float xr = x - __uint_as_float(h << 16);
    float yr = y - __uint_as_float(h & 0xffff0000u);
    hi = h;
    lo = pk(xr, yr);
}

// m16n8k16 bf16 MMA, f32 accumulate (A row-major, B col-major)
__device__ __forceinline__ void mma_bf16(float* c, const uint32_t* a,
                                         uint32_t b0, uint32_t b1) {
    asm volatile(
        "mma.sync.aligned.m16n8k16.row.col.f32.bf16.bf16.f32 "
        "{%0,%1,%2,%3}, {%4,%5,%6,%7}, {%8,%9}, {%0,%1,%2,%3};"
        : "+f"(c[0]), "+f"(c[1]), "+f"(c[2]), "+f"(c[3])
        : "r"(a[0]), "r"(a[1]), "r"(a[2]), "r"(a[3]), "r"(b0), "r"(b1));
}

// ---------------------------------------------------------------------------
// Pack adj (int32 0/1, [N,N]) into bitmask words: g_mask[row*128 + w] bit i
// = adj[row, 32w+i] > 0.
// ---------------------------------------------------------------------------
__global__ __launch_bounds__(256) void pack_mask(
    const int* __restrict__ adj, uint32_t* __restrict__ mb)
{
    int w = blockIdx.x * blockDim.x + threadIdx.x;   // word index
    const int4* p = (const int4*)(adj + (size_t)w * 32);
    uint32_t bits = 0;
#pragma unroll
    for (int i = 0; i < 8; i++) {
        int4 a = p[i];
        bits |= (a.x > 0 ? 1u : 0u) << (4 * i + 0);
        bits |= (a.y > 0 ? 1u : 0u) << (4 * i + 1);
        bits |= (a.z > 0 ? 1u : 0u) << (4 * i + 2);
        bits |= (a.w > 0 ? 1u : 0u) << (4 * i + 3);
    }
    mb[w] = bits;
}

// ---------------------------------------------------------------------------
// GEMM: Y[m][n] = sum_k A[m][k]*B[n][k] (+bias). 64x64 tile, 256 thr. (as R4)
// ---------------------------------------------------------------------------
__global__ __launch_bounds__(256) void gemm_nt(
    const float* __restrict__ A, const float* __restrict__ B,
    const float* __restrict__ bias, float* __restrict__ Y,
    int M, int Nn, int K)
{
    __shared__ float As[16][68];
    __shared__ float Bs[16][68];

    const int tid = threadIdx.x;
    const int tx = tid & 15;
    const int ty = tid >> 4;
    const int m0 = blockIdx.y << 6;
    const int n0 = blockIdx.x << 6;
    const int lr = tid >> 2;
    const int lk = (tid & 3) << 2;

    const float* Ap = A + (size_t)(m0 + lr) * K + lk;
    const float* Bp = B + (size_t)(n0 + lr) * K + lk;

    float c[4][4];
#pragma unroll
    for (int i = 0; i < 4; i++)
#pragma unroll
        for (int j = 0; j < 4; j++) c[i][j] = 0.0f;

    float4 av = *(const float4*)(Ap);
    float4 bv = *(const float4*)(Bp);

    for (int k0 = 0; k0 < K; k0 += 16) {
        __syncthreads();
        As[lk + 0][lr] = av.x; As[lk + 1][lr] = av.y;
        As[lk + 2][lr] = av.z; As[lk + 3][lr] = av.w;
        Bs[lk + 0][lr] = bv.x; Bs[lk + 1][lr] = bv.y;
        Bs[lk + 2][lr] = bv.z; Bs[lk + 3][lr] = bv.w;
        __syncthreads();
        if (k0 + 16 < K) {
            av = *(const float4*)(Ap + k0 + 16);
            bv = *(const float4*)(Bp + k0 + 16);
        }
#pragma unroll
        for (int kk = 0; kk < 16; kk++) {
            float4 a = *(const float4*)&As[kk][ty << 2];
            float4 b = *(const float4*)&Bs[kk][tx << 2];
            c[0][0] = fmaf(a.x, b.x, c[0][0]); c[0][1] = fmaf(a.x, b.y, c[0][1]);
            c[0][2] = fmaf(a.x, b.z, c[0][2]); c[0][3] = fmaf(a.x, b.w, c[0][3]);
            c[1][0] = fmaf(a.y, b.x, c[1][0]); c[1][1] = fmaf(a.y, b.y, c[1][1]);
            c[1][2] = fmaf(a.y, b.z, c[1][2]); c[1][3] = fmaf(a.y, b.w, c[1][3]);
            c[2][0] = fmaf(a.z, b.x, c[2][0]); c[2][1] = fmaf(a.z, b.y, c[2][1]);
            c[2][2] = fmaf(a.z, b.z, c[2][2]); c[2][3] = fmaf(a.z, b.w, c[2][3]);
            c[3][0] = fmaf(a.w, b.x, c[3][0]); c[3][1] = fmaf(a.w, b.y, c[3][1]);
            c[3][2] = fmaf(a.w, b.z, c[3][2]); c[3][3] = fmaf(a.w, b.w, c[3][3]);
        }
    }

    float b0 = 0.f, b1 = 0.f, b2 = 0.f, b3 = 0.f;
    if (bias) {
        const int nb = n0 + (tx << 2);
        b0 = bias[nb + 0]; b1 = bias[nb + 1]; b2 = bias[nb + 2]; b3 = bias[nb + 3];
    }
#pragma unroll
    for (int i = 0; i < 4; i++) {
        const int mrow = m0 + (ty << 2) + i;
        float4 o;
        o.x = c[i][0] + b0; o.y = c[i][1] + b1;
        o.z = c[i][2] + b2; o.w = c[i][3] + b3;
        *(float4*)(Y + (size_t)mrow * Nn + n0 + (tx << 2)) = o;
    }
}

// ---------------------------------------------------------------------------
// Tensor-core flash attention with 2xBF16 split precision.
// Block: 64 q-rows x 1 head, 128 threads = 4 warps (16 rows each).
// Per warp-lane: group g = lane>>4? no: g = lane/4, t = lane%4 (mma layout).
// S = Q.K^T via m16n8k16 bf16 mma (3-term hi/lo split), mask from packed
// bitmask, online softmax in registers (base-2), P.V via mma (3-term split,
// P fragments map in-thread from S accumulators).
// smem: K hi/lo [64 keys][40 bf16] (stride 40 -> conflict-free B-frag LDS),
//       V^T hi/lo [32 dh][72 keys] (stride 72 -> conflict-free).
// ---------------------------------------------------------------------------
__global__ __launch_bounds__(128, 3) void attn_tc(
    const float* __restrict__ qkv, const uint32_t* __restrict__ mb,
    float* __restrict__ out)
{
    __shared__ uint16_t Khi[64 * 40];
    __shared__ uint16_t Klo[64 * 40];
    __shared__ uint16_t Vthi[32 * 72];
    __shared__ uint16_t Vtlo[32 * 72];

    const int tid  = threadIdx.x;
    const int w    = tid >> 5;
    const int lane = tid & 31;
    const int g    = lane >> 2;
    const int t    = lane & 3;
    const int h    = blockIdx.y;
    const int q0   = blockIdx.x << 6;
    const int rA   = q0 + w * 16 + g;
    const int rB   = rA + 8;
    const float qscale = 0.17677669529663687f * 1.4426950408889634f;

    // ---- load Q rows rA, rB into A-fragment registers (hi/lo bf16) ----
    uint32_t qhi[2][4], qlo[2][4];
    {
        const float* qpA = qkv + (size_t)rA * 768 + h * 32 + 2 * t;
        const float* qpB = qkv + (size_t)rB * 768 + h * 32 + 2 * t;
        float fA[8], fB[8];
#pragma unroll
        for (int j = 0; j < 4; j++) {
            float2 a = *(const float2*)(qpA + 8 * j);
            float2 b = *(const float2*)(qpB + 8 * j);
            fA[2 * j] = a.x * qscale; fA[2 * j + 1] = a.y * qscale;
            fB[2 * j] = b.x * qscale; fB[2 * j + 1] = b.y * qscale;
        }
#pragma unroll
        for (int s = 0; s < 2; s++) {
            split2(fA[4 * s + 0], fA[4 * s + 1], qhi[s][0], qlo[s][0]);
            split2(fB[4 * s + 0], fB[4 * s + 1], qhi[s][1], qlo[s][1]);
            split2(fA[4 * s + 2], fA[4 * s + 3], qhi[s][2], qlo[s][2]);
            split2(fB[4 * s + 2], fB[4 * s + 3], qhi[s][3], qlo[s][3]);
        }
    }

    float mA = MINIT, mB = MINIT, lA = 0.0f, lB = 0.0f;
    float o[4][4];
#pragma unroll
    for (int n = 0; n < 4; n++)
#pragma unroll
        for (int i = 0; i < 4; i++) o[n][i] = 0.0f;

    // loader mapping: row lr (key), 16-float half lc
    const int lr = tid >> 1;
    const int lc = (tid & 1) * 16;
    const float* kbg = qkv + (size_t)lr * 768 + 256 + h * 32 + lc;
    const float* vbg = kbg + 256;

    float4 kr[4], vr[4];
#pragma unroll
    for (int i = 0; i < 4; i++) {
        kr[i] = ((const float4*)kbg)[i];
        vr[i] = ((const float4*)vbg)[i];
    }

    for (int T = 0; T < 64; T++) {
        __syncthreads();
        // store K tile (hi/lo) : row lr, cols lc..lc+15
#pragma unroll
        for (int i = 0; i < 4; i++) {
            uint32_t h0, l0, h1, l1;
            split2(kr[i].x, kr[i].y, h0, l0);
            split2(kr[i].z, kr[i].w, h1, l1);
            const int base = lr * 40 + lc + 4 * i;
            *(uint32_t*)&Khi[base]     = h0;
            *(uint32_t*)&Khi[base + 2] = h1;
            *(uint32_t*)&Klo[base]     = l0;
            *(uint32_t*)&Klo[base + 2] = l1;
        }
        // store V^T tile (hi/lo): dh rows, key col lr
#pragma unroll
        for (int i = 0; i < 4; i++) {
            float f[4] = {vr[i].x, vr[i].y, vr[i].z, vr[i].w};
#pragma unroll
            for (int cpt = 0; cpt < 4; cpt++) {
                const int dh = lc + 4 * i + cpt;
                uint32_t hb = pk(f[cpt], 0.0f);
                float fr = f[cpt] - __uint_as_float(hb << 16);
                uint32_t lb = pk(fr, 0.0f);
                Vthi[dh * 72 + lr] = (uint16_t)(hb & 0xffffu);
                Vtlo[dh * 72 + lr] = (uint16_t)(lb & 0xffffu);
            }
        }
        __syncthreads();

        // prefetch next tile
        if (T < 63) {
            const float4* kp = (const float4*)(kbg + (size_t)(T + 1) * 64 * 768);
            const float4* vp = (const float4*)(vbg + (size_t)(T + 1) * 64 * 768);
#pragma unroll
            for (int i = 0; i < 4; i++) { kr[i] = kp[i]; vr[i] = vp[i]; }
        }

        // mask words for this 64-key tile (2 words per row)
        const uint32_t wA0 = mb[(size_t)rA * 128 + 2 * T];
        const uint32_t wA1 = mb[(size_t)rA * 128 + 2 * T + 1];
        const uint32_t wB0 = mb[(size_t)rB * 128 + 2 * T];
        const uint32_t wB1 = mb[(size_t)rB * 128 + 2 * T + 1];

        // ---- S = Q.K^T : 8 n-tiles, 2 k-steps, 3 split terms ----
        float c[8][4];
#pragma unroll
        for (int n = 0; n < 8; n++)
#pragma unroll
            for (int i = 0; i < 4; i++) c[n][i] = 0.0f;

#pragma unroll
        for (int n = 0; n < 8; n++) {
            const int krow = (8 * n + g) * 40;
#pragma unroll
            for (int s = 0; s < 2; s++) {
                const int off = krow + 16 * s + 2 * t;
                uint32_t bh0 = *(const uint32_t*)&Khi[off];
                uint32_t bh1 = *(const uint32_t*)&Khi[off + 8];
                uint32_t bl0 = *(const uint32_t*)&Klo[off];
                uint32_t bl1 = *(const uint32_t*)&Klo[off + 8];
                mma_bf16(c[n], qhi[s], bh0, bh1);
                mma_bf16(c[n], qhi[s], bl0, bl1);
                mma_bf16(c[n], qlo[s], bh0, bh1);
            }
        }

        // ---- mask ----
#pragma unroll
        for (int n = 0; n < 8; n++) {
            const int sh = (8 * n + 2 * t) & 31;
            uint32_t bA = ((n < 4) ? wA0 : wA1) >> sh;
            uint32_t bB = ((n < 4) ? wB0 : wB1) >> sh;
            if (!(bA & 1u)) c[n][0] = NEGBIG;
            if (!(bA & 2u)) c[n][1] = NEGBIG;
            if (!(bB & 1u)) c[n][2] = NEGBIG;
            if (!(bB & 2u)) c[n][3] = NEGBIG;
        }

        // ---- online softmax (base-2), rows rA (c0,c1) and rB (c2,c3) ----
        float mlA = c[0][0], mlB = c[0][2];
#pragma unroll
        for (int n = 0; n < 8; n++) {
            mlA = fmaxf(mlA, fmaxf(c[n][0], c[n][1]));
            mlB = fmaxf(mlB, fmaxf(c[n][2], c[n][3]));
        }
        mlA = fmaxf(mlA, __shfl_xor_sync(0xffffffffu, mlA, 1));
        mlA = fmaxf(mlA, __shfl_xor_sync(0xffffffffu, mlA, 2));
        mlB = fmaxf(mlB, __shfl_xor_sync(0xffffffffu, mlB, 1));
        mlB = fmaxf(mlB, __shfl_xor_sync(0xffffffffu, mlB, 2));

        const float mnA = fmaxf(mA, mlA);
        const float mnB = fmaxf(mB, mlB);
        const float cA = ex2(mA - mnA);
        const float cB = ex2(mB - mnB);
        mA = mnA; mB = mnB;

        float lsA = 0.0f, lsB = 0.0f;
#pragma unroll
        for (int n = 0; n < 8; n++) {
            c[n][0] = ex2(c[n][0] - mnA);
            c[n][1] = ex2(c[n][1] - mnA);
            c[n][2] = ex2(c[n][2] - mnB);
            c[n][3] = ex2(c[n][3] - mnB);
            lsA += c[n][0] + c[n][1];
            lsB += c[n][2] + c[n][3];
        }
        lsA += __shfl_xor_sync(0xffffffffu, lsA, 1);
        lsA += __shfl_xor_sync(0xffffffffu, lsA, 2);
        lsB += __shfl_xor_sync(0xffffffffu, lsB, 1);
        lsB += __shfl_xor_sync(0xffffffffu, lsB, 2);
        lA = fmaf(lA, cA, lsA);
        lB = fmaf(lB, cB, lsB);

#pragma unroll
        for (int n = 0; n < 4; n++) {
            o[n][0] *= cA; o[n][1] *= cA;
            o[n][2] *= cB; o[n][3] *= cB;
        }

        // ---- out += P.V : 4 k-steps (16 keys), 4 dh-tiles, 3 split terms ----
#pragma unroll
        for (int s = 0; s < 4; s++) {
            uint32_t ph[4], pl[4];
            split2(c[2 * s][0],     c[2 * s][1],     ph[0], pl[0]);
            split2(c[2 * s][2],     c[2 * s][3],     ph[1], pl[1]);
            split2(c[2 * s + 1][0], c[2 * s + 1][1], ph[2], pl[2]);
            split2(c[2 * s + 1][2], c[2 * s + 1][3], ph[3], pl[3]);
#pragma unroll
            for (int n = 0; n < 4; n++) {
                const int off = (8 * n + g) * 72 + 16 * s + 2 * t;
                uint32_t bh0 = *(const uint32_t*)&Vthi[off];
                uint32_t bh1 = *(const uint32_t*)&Vthi[off + 8];
                uint32_t bl0 = *(const uint32_t*)&Vtlo[off];
                uint32_t bl1 = *(const uint32_t*)&Vtlo[off + 8];
                mma_bf16(o[n], ph, bh0, bh1);
                mma_bf16(o[n], ph, bl0, bl1);
                mma_bf16(o[n], pl, bh0, bh1);
            }
        }
    }

    // ---- normalize + store ----
    const float invA = 1.0f / lA;
    const float invB = 1.0f / lB;
    float* opA = out + (size_t)rA * 256 + h * 32 + 2 * t;
    float* opB = out + (size_t)rB * 256 + h * 32 + 2 * t;
#pragma unroll
    for (int n = 0; n < 4; n++) {
        float2 oa; oa.x = o[n][0] * invA; oa.y = o[n][1] * invA;
        float2 ob; ob.x = o[n][2] * invB; ob.y = o[n][3] * invB;
        *(float2*)(opA + 8 * n) = oa;
        *(float2*)(opB + 8 * n) = ob;
    }
}

// ---------------------------------------------------------------------------
extern "C" void kernel_launch(void* const* d_in, const int* in_sizes, int n_in,
                              void* d_out, int out_size)
{
    const float* x      = (const float*)d_in[0];
    const int*   adj    = (const int*)d_in[1];
    const float* w_qkv  = (const float*)d_in[2];
    const float* w_proj = (const float*)d_in[3];
    const float* b_proj = (const float*)d_in[4];
    float*       out    = (float*)d_out;

    void *p1 = nullptr, *p2 = nullptr, *p3 = nullptr;
    cudaGetSymbolAddress(&p1, g_qkv);
    cudaGetSymbolAddress(&p2, g_att);
    cudaGetSymbolAddress(&p3, g_mask);
    float*    qkv = (float*)p1;
    float*    att = (float*)p2;
    uint32_t* msk = (uint32_t*)p3;

    // 0) pack adj into bitmask (2 MB, L2-resident afterwards)
    pack_mask<<<(NTOK * (NTOK / 32)) / 256, 256>>>(adj, msk);
    // 1) QKV projection
    {
        dim3 grid(768 / 64, NTOK / 64);
        gemm_nt<<<grid, 256>>>(x, w_qkv, nullptr, qkv, NTOK, 3 * CDIM, CDIM);
    }
    // 2) tensor-core masked flash attention
    {
        dim3 grid(NTOK / 64, HEADS);
        attn_tc<<<grid, 128>>>(qkv, msk, att);
    }
    // 3) output projection + bias
    {
        dim3 grid(CDIM / 64, NTOK / 64);
        gemm_nt<<<grid, 256>>>(att, w_proj, b_proj, out, NTOK, CDIM, CDIM);
    }
}

// round 6
// speedup vs baseline: 4.3104x; 1.1885x over previous
#include <cuda_runtime.h>
#include <cuda_fp16.h>
#include <cstdint>

#define NTOK 4096
#define CDIM 256
#define HEADS 8
#define NEGBIG (-1.0e30f)
#define MINIT  (-1.0e4f)   // softmax max floor; any true score is >> this

// scratch (allocation-free rule: device globals)
__device__ float    g_qkv[NTOK * 3 * CDIM];       // [N, 3*C] (q|k|v)
__device__ float    g_att[NTOK * CDIM];           // attention output [N, C]
__device__ uint32_t g_mask[NTOK * (NTOK / 32)];   // packed adj bitmask, 2 MB

__device__ __forceinline__ float ex2(float x) {
    float y;
    asm("ex2.approx.ftz.f32 %0, %1;" : "=f"(y) : "f"(x));
    return y;
}

// pack two floats -> f16x2 (x in low half, y in high half)
__device__ __forceinline__ uint32_t pkh(float x, float y) {
    uint32_t r;
    asm("cvt.rn.f16x2.f32 %0, %1, %2;" : "=r"(r) : "f"(y), "f"(x));
    return r;
}

// split (x,y) into hi f16x2 and lo f16x2 residuals
__device__ __forceinline__ void splith(float x, float y, uint32_t& hi, uint32_t& lo) {
    uint32_t h = pkh(x, y);
    float xh, yh;
    asm("{ .reg .f16 a,b;\n"
        "  mov.b32 {a,b}, %2;\n"
        "  cvt.f32.f16 %0, a;\n"
        "  cvt.f32.f16 %1, b; }"
        : "=f"(xh), "=f"(yh) : "r"(h));
    hi = h;
    lo = pkh(x - xh, y - yh);
}

// m16n8k16 fp16 MMA, f32 accumulate (A row-major, B col-major)
__device__ __forceinline__ void mma_f16(float* c, const uint32_t* a,
                                        uint32_t b0, uint32_t b1) {
    asm volatile(
        "mma.sync.aligned.m16n8k16.row.col.f32.f16.f16.f32 "
        "{%0,%1,%2,%3}, {%4,%5,%6,%7}, {%8,%9}, {%0,%1,%2,%3};"
        : "+f"(c[0]), "+f"(c[1]), "+f"(c[2]), "+f"(c[3])
        : "r"(a[0]), "r"(a[1]), "r"(a[2]), "r"(a[3]), "r"(b0), "r"(b1));
}

// ---------------------------------------------------------------------------
// Pack adj (int32 0/1, [N,N]) into bitmask words.
// ---------------------------------------------------------------------------
__global__ __launch_bounds__(256) void pack_mask(
    const int* __restrict__ adj, uint32_t* __restrict__ mb)
{
    int w = blockIdx.x * blockDim.x + threadIdx.x;
    const int4* p = (const int4*)(adj + (size_t)w * 32);
    uint32_t bits = 0;
#pragma unroll
    for (int i = 0; i < 8; i++) {
        int4 a = p[i];
        bits |= (a.x > 0 ? 1u : 0u) << (4 * i + 0);
        bits |= (a.y > 0 ? 1u : 0u) << (4 * i + 1);
        bits |= (a.z > 0 ? 1u : 0u) << (4 * i + 2);
        bits |= (a.w > 0 ? 1u : 0u) << (4 * i + 3);
    }
    mb[w] = bits;
}

// ---------------------------------------------------------------------------
// GEMM: Y[m][n] = sum_k A[m][k]*B[n][k] (+bias). 64x64 tile, 256 thr.
// ---------------------------------------------------------------------------
__global__ __launch_bounds__(256) void gemm_nt(
    const float* __restrict__ A, const float* __restrict__ B,
    const float* __restrict__ bias, float* __restrict__ Y,
    int M, int Nn, int K)
{
    __shared__ float As[16][68];
    __shared__ float Bs[16][68];

    const int tid = threadIdx.x;
    const int tx = tid & 15;
    const int ty = tid >> 4;
    const int m0 = blockIdx.y << 6;
    const int n0 = blockIdx.x << 6;
    const int lr = tid >> 2;
    const int lk = (tid & 3) << 2;

    const float* Ap = A + (size_t)(m0 + lr) * K + lk;
    const float* Bp = B + (size_t)(n0 + lr) * K + lk;

    float c[4][4];
#pragma unroll
    for (int i = 0; i < 4; i++)
#pragma unroll
        for (int j = 0; j < 4; j++) c[i][j] = 0.0f;

    float4 av = *(const float4*)(Ap);
    float4 bv = *(const float4*)(Bp);

    for (int k0 = 0; k0 < K; k0 += 16) {
        __syncthreads();
        As[lk + 0][lr] = av.x; As[lk + 1][lr] = av.y;
        As[lk + 2][lr] = av.z; As[lk + 3][lr] = av.w;
        Bs[lk + 0][lr] = bv.x; Bs[lk + 1][lr] = bv.y;
        Bs[lk + 2][lr] = bv.z; Bs[lk + 3][lr] = bv.w;
        __syncthreads();
        if (k0 + 16 < K) {
            av = *(const float4*)(Ap + k0 + 16);
            bv = *(const float4*)(Bp + k0 + 16);
        }
#pragma unroll
        for (int kk = 0; kk < 16; kk++) {
            float4 a = *(const float4*)&As[kk][ty << 2];
            float4 b = *(const float4*)&Bs[kk][tx << 2];
            c[0][0] = fmaf(a.x, b.x, c[0][0]); c[0][1] = fmaf(a.x, b.y, c[0][1]);
            c[0][2] = fmaf(a.x, b.z, c[0][2]); c[0][3] = fmaf(a.x, b.w, c[0][3]);
            c[1][0] = fmaf(a.y, b.x, c[1][0]); c[1][1] = fmaf(a.y, b.y, c[1][1]);
            c[1][2] = fmaf(a.y, b.z, c[1][2]); c[1][3] = fmaf(a.y, b.w, c[1][3]);
            c[2][0] = fmaf(a.z, b.x, c[2][0]); c[2][1] = fmaf(a.z, b.y, c[2][1]);
            c[2][2] = fmaf(a.z, b.z, c[2][2]); c[2][3] = fmaf(a.z, b.w, c[2][3]);
            c[3][0] = fmaf(a.w, b.x, c[3][0]); c[3][1] = fmaf(a.w, b.y, c[3][1]);
            c[3][2] = fmaf(a.w, b.z, c[3][2]); c[3][3] = fmaf(a.w, b.w, c[3][3]);
        }
    }

    float b0 = 0.f, b1 = 0.f, b2 = 0.f, b3 = 0.f;
    if (bias) {
        const int nb = n0 + (tx << 2);
        b0 = bias[nb + 0]; b1 = bias[nb + 1]; b2 = bias[nb + 2]; b3 = bias[nb + 3];
    }
#pragma unroll
    for (int i = 0; i < 4; i++) {
        const int mrow = m0 + (ty << 2) + i;
        float4 o;
        o.x = c[i][0] + b0; o.y = c[i][1] + b1;
        o.z = c[i][2] + b2; o.w = c[i][3] + b3;
        *(float4*)(Y + (size_t)mrow * Nn + n0 + (tx << 2)) = o;
    }
}

// ---------------------------------------------------------------------------
// Tensor-core flash attention, 2-term FP16 split precision.
// Block: 64 q-rows x 1 head, 128 threads = 4 warps (16 rows each).
// QK^T: S = q_hi.K_hi + q_lo.K_hi  (K residual dropped: error decorrelated
//       across keys -> averaged out by softmax).
// PV:   O += p_hi.V_hi + p_hi.V_lo (P residual dropped: same argument).
// smem: K hi [64 keys][40 f16], V^T hi/lo [32 dh][72 f16].
// ---------------------------------------------------------------------------
__global__ __launch_bounds__(128, 3) void attn_tc(
    const float* __restrict__ qkv, const uint32_t* __restrict__ mb,
    float* __restrict__ out)
{
    __shared__ uint16_t Khi[64 * 40];
    __shared__ uint16_t Vthi[32 * 72];
    __shared__ uint16_t Vtlo[32 * 72];

    const int tid  = threadIdx.x;
    const int w    = tid >> 5;
    const int lane = tid & 31;
    const int g    = lane >> 2;
    const int t    = lane & 3;
    const int h    = blockIdx.y;
    const int q0   = blockIdx.x << 6;
    const int rA   = q0 + w * 16 + g;
    const int rB   = rA + 8;
    const float qscale = 0.17677669529663687f * 1.4426950408889634f;

    // ---- load Q rows rA, rB into A-fragments (fp16 hi + lo residual) ----
    uint32_t qhi[2][4], qlo[2][4];
    {
        const float* qpA = qkv + (size_t)rA * 768 + h * 32 + 2 * t;
        const float* qpB = qkv + (size_t)rB * 768 + h * 32 + 2 * t;
        float fA[8], fB[8];
#pragma unroll
        for (int j = 0; j < 4; j++) {
            float2 a = *(const float2*)(qpA + 8 * j);
            float2 b = *(const float2*)(qpB + 8 * j);
            fA[2 * j] = a.x * qscale; fA[2 * j + 1] = a.y * qscale;
            fB[2 * j] = b.x * qscale; fB[2 * j + 1] = b.y * qscale;
        }
#pragma unroll
        for (int s = 0; s < 2; s++) {
            splith(fA[4 * s + 0], fA[4 * s + 1], qhi[s][0], qlo[s][0]);
            splith(fB[4 * s + 0], fB[4 * s + 1], qhi[s][1], qlo[s][1]);
            splith(fA[4 * s + 2], fA[4 * s + 3], qhi[s][2], qlo[s][2]);
            splith(fB[4 * s + 2], fB[4 * s + 3], qhi[s][3], qlo[s][3]);
        }
    }

    float mA = MINIT, mB = MINIT, lA = 0.0f, lB = 0.0f;
    float o[4][4];
#pragma unroll
    for (int n = 0; n < 4; n++)
#pragma unroll
        for (int i = 0; i < 4; i++) o[n][i] = 0.0f;

    // K loader: thread owns key klr, 16-dh chunk klc
    const int klr = tid >> 1;
    const int klc = (tid & 1) * 16;
    const float* kbg = qkv + (size_t)klr * 768 + 256 + h * 32 + klc;
    // V loader: thread owns keys {2vj, 2vj+1}, 8-dh chunk vc
    const int vj = tid >> 2;
    const int vc = (tid & 3) * 8;
    const float* vbg = qkv + (size_t)(2 * vj) * 768 + 512 + h * 32 + vc;

    float4 kr[4], vr[4];
#pragma unroll
    for (int i = 0; i < 4; i++) kr[i] = ((const float4*)kbg)[i];
    vr[0] = ((const float4*)vbg)[0];
    vr[1] = ((const float4*)vbg)[1];
    vr[2] = ((const float4*)(vbg + 768))[0];
    vr[3] = ((const float4*)(vbg + 768))[1];

    for (int T = 0; T < 64; T++) {
        __syncthreads();
        // store K tile (hi only), fp16
#pragma unroll
        for (int i = 0; i < 4; i++) {
            const int base = klr * 40 + klc + 4 * i;
            *(uint32_t*)&Khi[base]     = pkh(kr[i].x, kr[i].y);
            *(uint32_t*)&Khi[base + 2] = pkh(kr[i].z, kr[i].w);
        }
        // store V^T tile (hi/lo): 32-bit stores covering keys {2vj, 2vj+1}
        {
            float a[8] = {vr[0].x, vr[0].y, vr[0].z, vr[0].w,
                          vr[1].x, vr[1].y, vr[1].z, vr[1].w};
            float b[8] = {vr[2].x, vr[2].y, vr[2].z, vr[2].w,
                          vr[3].x, vr[3].y, vr[3].z, vr[3].w};
#pragma unroll
            for (int d = 0; d < 8; d++) {
                uint32_t hi, lo;
                splith(a[d], b[d], hi, lo);   // low half = key 2vj
                *(uint32_t*)&Vthi[(vc + d) * 72 + 2 * vj] = hi;
                *(uint32_t*)&Vtlo[(vc + d) * 72 + 2 * vj] = lo;
            }
        }
        __syncthreads();

        // prefetch next tile
        if (T < 63) {
            const size_t off = (size_t)(T + 1) * 64 * 768;
            const float4* kp = (const float4*)(kbg + off);
#pragma unroll
            for (int i = 0; i < 4; i++) kr[i] = kp[i];
            vr[0] = ((const float4*)(vbg + off))[0];
            vr[1] = ((const float4*)(vbg + off))[1];
            vr[2] = ((const float4*)(vbg + off + 768))[0];
            vr[3] = ((const float4*)(vbg + off + 768))[1];
        }

        // mask words for this 64-key tile
        const uint32_t wA0 = mb[(size_t)rA * 128 + 2 * T];
        const uint32_t wA1 = mb[(size_t)rA * 128 + 2 * T + 1];
        const uint32_t wB0 = mb[(size_t)rB * 128 + 2 * T];
        const uint32_t wB1 = mb[(size_t)rB * 128 + 2 * T + 1];

        // ---- S = Q.K^T : 8 n-tiles x 2 k-steps x 2 split terms ----
        float c[8][4];
#pragma unroll
        for (int n = 0; n < 8; n++)
#pragma unroll
            for (int i = 0; i < 4; i++) c[n][i] = 0.0f;

#pragma unroll
        for (int n = 0; n < 8; n++) {
            const int krow = (8 * n + g) * 40;
#pragma unroll
            for (int s = 0; s < 2; s++) {
                const int off = krow + 16 * s + 2 * t;
                uint32_t bh0 = *(const uint32_t*)&Khi[off];
                uint32_t bh1 = *(const uint32_t*)&Khi[off + 8];
                mma_f16(c[n], qhi[s], bh0, bh1);
                mma_f16(c[n], qlo[s], bh0, bh1);
            }
        }

        // ---- mask ----
#pragma unroll
        for (int n = 0; n < 8; n++) {
            const int sh = (8 * n + 2 * t) & 31;
            uint32_t bA = ((n < 4) ? wA0 : wA1) >> sh;
            uint32_t bB = ((n < 4) ? wB0 : wB1) >> sh;
            if (!(bA & 1u)) c[n][0] = NEGBIG;
            if (!(bA & 2u)) c[n][1] = NEGBIG;
            if (!(bB & 1u)) c[n][2] = NEGBIG;
            if (!(bB & 2u)) c[n][3] = NEGBIG;
        }

        // ---- online softmax (base-2) ----
        float mlA = c[0][0], mlB = c[0][2];
#pragma unroll
        for (int n = 0; n < 8; n++) {
            mlA = fmaxf(mlA, fmaxf(c[n][0], c[n][1]));
            mlB = fmaxf(mlB, fmaxf(c[n][2], c[n][3]));
        }
        mlA = fmaxf(mlA, __shfl_xor_sync(0xffffffffu, mlA, 1));
        mlA = fmaxf(mlA, __shfl_xor_sync(0xffffffffu, mlA, 2));
        mlB = fmaxf(mlB, __shfl_xor_sync(0xffffffffu, mlB, 1));
        mlB = fmaxf(mlB, __shfl_xor_sync(0xffffffffu, mlB, 2));

        const float mnA = fmaxf(mA, mlA);
        const float mnB = fmaxf(mB, mlB);
        const float cA = ex2(mA - mnA);
        const float cB = ex2(mB - mnB);
        mA = mnA; mB = mnB;

        float lsA = 0.0f, lsB = 0.0f;
#pragma unroll
        for (int n = 0; n < 8; n++) {
            c[n][0] = ex2(c[n][0] - mnA);
            c[n][1] = ex2(c[n][1] - mnA);
            c[n][2] = ex2(c[n][2] - mnB);
            c[n][3] = ex2(c[n][3] - mnB);
            lsA += c[n][0] + c[n][1];
            lsB += c[n][2] + c[n][3];
        }
        lsA += __shfl_xor_sync(0xffffffffu, lsA, 1);
        lsA += __shfl_xor_sync(0xffffffffu, lsA, 2);
        lsB += __shfl_xor_sync(0xffffffffu, lsB, 1);
        lsB += __shfl_xor_sync(0xffffffffu, lsB, 2);
        lA = fmaf(lA, cA, lsA);
        lB = fmaf(lB, cB, lsB);

#pragma unroll
        for (int n = 0; n < 4; n++) {
            o[n][0] *= cA; o[n][1] *= cA;
            o[n][2] *= cB; o[n][3] *= cB;
        }

        // ---- out += P.V : 4 k-steps x 4 dh-tiles x 2 split terms ----
#pragma unroll
        for (int s = 0; s < 4; s++) {
            uint32_t ph[4];
            ph[0] = pkh(c[2 * s][0],     c[2 * s][1]);
            ph[1] = pkh(c[2 * s][2],     c[2 * s][3]);
            ph[2] = pkh(c[2 * s + 1][0], c[2 * s + 1][1]);
            ph[3] = pkh(c[2 * s + 1][2], c[2 * s + 1][3]);
#pragma unroll
            for (int n = 0; n < 4; n++) {
                const int off = (8 * n + g) * 72 + 16 * s + 2 * t;
                uint32_t bh0 = *(const uint32_t*)&Vthi[off];
                uint32_t bh1 = *(const uint32_t*)&Vthi[off + 8];
                uint32_t bl0 = *(const uint32_t*)&Vtlo[off];
                uint32_t bl1 = *(const uint32_t*)&Vtlo[off + 8];
                mma_f16(o[n], ph, bh0, bh1);
                mma_f16(o[n], ph, bl0, bl1);
            }
        }
    }

    // ---- normalize + store ----
    const float invA = 1.0f / lA;
    const float invB = 1.0f / lB;
    float* opA = out + (size_t)rA * 256 + h * 32 + 2 * t;
    float* opB = out + (size_t)rB * 256 + h * 32 + 2 * t;
#pragma unroll
    for (int n = 0; n < 4; n++) {
        float2 oa; oa.x = o[n][0] * invA; oa.y = o[n][1] * invA;
        float2 ob; ob.x = o[n][2] * invB; ob.y = o[n][3] * invB;
        *(float2*)(opA + 8 * n) = oa;
        *(float2*)(opB + 8 * n) = ob;
    }
}

// ---------------------------------------------------------------------------
extern "C" void kernel_launch(void* const* d_in, const int* in_sizes, int n_in,
                              void* d_out, int out_size)
{
    const float* x      = (const float*)d_in[0];
    const int*   adj    = (const int*)d_in[1];
    const float* w_qkv  = (const float*)d_in[2];
    const float* w_proj = (const float*)d_in[3];
    const float* b_proj = (const float*)d_in[4];
    float*       out    = (float*)d_out;

    void *p1 = nullptr, *p2 = nullptr, *p3 = nullptr;
    cudaGetSymbolAddress(&p1, g_qkv);
    cudaGetSymbolAddress(&p2, g_att);
    cudaGetSymbolAddress(&p3, g_mask);
    float*    qkv = (float*)p1;
    float*    att = (float*)p2;
    uint32_t* msk = (uint32_t*)p3;

    // 0) pack adj into bitmask (2 MB, L2-resident afterwards)
    pack_mask<<<(NTOK * (NTOK / 32)) / 256, 256>>>(adj, msk);
    // 1) QKV projection
    {
        dim3 grid(768 / 64, NTOK / 64);
        gemm_nt<<<grid, 256>>>(x, w_qkv, nullptr, qkv, NTOK, 3 * CDIM, CDIM);
    }
    // 2) tensor-core masked flash attention
    {
        dim3 grid(NTOK / 64, HEADS);
        attn_tc<<<grid, 128>>>(qkv, msk, att);
    }
    // 3) output projection + bias
    {
        dim3 grid(CDIM / 64, NTOK / 64);
        gemm_nt<<<grid, 256>>>(att, w_proj, b_proj, out, NTOK, CDIM, CDIM);
    }
}

// round 8
// speedup vs baseline: 6.0728x; 1.4089x over previous
#include <cuda_runtime.h>
#include <cuda_fp16.h>
#include <cstdint>

#define NTOK 4096
#define CDIM 256
#define HEADS 8
#define NEGBIG (-1.0e30f)

// scratch (allocation-free rule: device globals)
__device__ float    g_qkv[NTOK * 3 * CDIM];        // [N, 3*C] (q|k|v) f32
__device__ uint32_t g_mask[NTOK * (NTOK / 32)];    // packed adj bitmask, 2 MB
__device__ uint16_t g_xhi[NTOK * CDIM],  g_xlo[NTOK * CDIM];        // x split
__device__ uint16_t g_wqh[3 * CDIM * CDIM], g_wql[3 * CDIM * CDIM]; // w_qkv split
__device__ uint16_t g_wph[CDIM * CDIM],  g_wpl[CDIM * CDIM];        // w_proj split
__device__ uint16_t g_ath[NTOK * CDIM],  g_atl[NTOK * CDIM];        // attn out split

// ---------------------------------------------------------------------------
// helpers
// ---------------------------------------------------------------------------
__device__ __forceinline__ float ex2(float x) {
    float y;
    asm("ex2.approx.ftz.f32 %0, %1;" : "=f"(y) : "f"(x));
    return y;
}
__device__ __forceinline__ uint32_t pkh(float x, float y) {  // f16x2(lo=x,hi=y)
    uint32_t r;
    asm("cvt.rn.f16x2.f32 %0, %1, %2;" : "=r"(r) : "f"(y), "f"(x));
    return r;
}
__device__ __forceinline__ void splith(float x, float y, uint32_t& hi, uint32_t& lo) {
    uint32_t h = pkh(x, y);
    float xh, yh;
    asm("{ .reg .f16 a,b;\n  mov.b32 {a,b}, %2;\n  cvt.f32.f16 %0, a;\n  cvt.f32.f16 %1, b; }"
        : "=f"(xh), "=f"(yh) : "r"(h));
    hi = h;
    lo = pkh(x - xh, y - yh);
}
// m16n8k16 fp16 MMA, f32 accumulate (A row-major, B col-major)
__device__ __forceinline__ void mma_f16(float* c, const uint32_t* a,
                                        uint32_t b0, uint32_t b1) {
    asm volatile(
        "mma.sync.aligned.m16n8k16.row.col.f32.f16.f16.f32 "
        "{%0,%1,%2,%3}, {%4,%5,%6,%7}, {%8,%9}, {%0,%1,%2,%3};"
        : "+f"(c[0]), "+f"(c[1]), "+f"(c[2]), "+f"(c[3])
        : "r"(a[0]), "r"(a[1]), "r"(a[2]), "r"(a[3]), "r"(b0), "r"(b1));
}

// ---------------------------------------------------------------------------
// pack adj into bitmask
// ---------------------------------------------------------------------------
__global__ __launch_bounds__(256) void pack_mask(
    const int* __restrict__ adj, uint32_t* __restrict__ mb)
{
    int w = blockIdx.x * blockDim.x + threadIdx.x;
    const int4* p = (const int4*)(adj + (size_t)w * 32);
    uint32_t bits = 0;
#pragma unroll
    for (int i = 0; i < 8; i++) {
        int4 a = p[i];
        bits |= (a.x > 0 ? 1u : 0u) << (4 * i + 0);
        bits |= (a.y > 0 ? 1u : 0u) << (4 * i + 1);
        bits |= (a.z > 0 ? 1u : 0u) << (4 * i + 2);
        bits |= (a.w > 0 ? 1u : 0u) << (4 * i + 3);
    }
    mb[w] = bits;
}

// ---------------------------------------------------------------------------
// pack f32 -> fp16 hi + fp16 lo residual (4 floats per thread)
// ---------------------------------------------------------------------------
__global__ __launch_bounds__(256) void pack_halves(
    const float* __restrict__ src, uint16_t* __restrict__ hi,
    uint16_t* __restrict__ lo)
{
    int i = blockIdx.x * blockDim.x + threadIdx.x;
    float4 f = ((const float4*)src)[i];
    uint32_t h01, l01, h23, l23;
    splith(f.x, f.y, h01, l01);
    splith(f.z, f.w, h23, l23);
    ((uint2*)hi)[i] = make_uint2(h01, h23);
    ((uint2*)lo)[i] = make_uint2(l01, l23);
}

// ---------------------------------------------------------------------------
// Split-fp16 tensor-core GEMM: Y[m][n] = sum_k A[m][k]*B[n][k] (+bias)
// 3-term split: Ah.Bh + Ah.Bl + Al.Bh (dropped lo.lo ~ 2^-24).
// Block tile 128x64, 256 threads (8 warps, 4x2), warp tile 32x32, BK=32.
// ---------------------------------------------------------------------------
__global__ __launch_bounds__(256) void gemm_tc(
    const uint16_t* __restrict__ Ahi, const uint16_t* __restrict__ Alo,
    const uint16_t* __restrict__ Bhi, const uint16_t* __restrict__ Blo,
    const float* __restrict__ bias, float* __restrict__ Y,
    int M, int Nn, int K)
{
    __shared__ uint16_t sA[2][128 * 40];   // [split][row][40] halves
    __shared__ uint16_t sB[2][64 * 40];

    const int tid = threadIdx.x;
    const int w    = tid >> 5;
    const int lane = tid & 31;
    const int g    = lane >> 2;
    const int t    = lane & 3;
    const int wm   = w >> 1;        // 0..3
    const int wn   = w & 1;         // 0..1
    const int m0 = blockIdx.y << 7;
    const int n0 = blockIdx.x << 6;

    // loaders
    const int ar = tid >> 1, ac = (tid & 1) * 16;   // A: 16 halves
    const int br = tid >> 2, bc = (tid & 3) * 8;    // B: 8 halves

    const uint16_t* Ah = Ahi + (size_t)(m0 + ar) * K + ac;
    const uint16_t* Al = Alo + (size_t)(m0 + ar) * K + ac;
    const uint16_t* Bh = Bhi + (size_t)(n0 + br) * K + bc;
    const uint16_t* Bl = Blo + (size_t)(n0 + br) * K + bc;

    float c[2][4][4];
#pragma unroll
    for (int i = 0; i < 2; i++)
#pragma unroll
        for (int n = 0; n < 4; n++)
#pragma unroll
            for (int j = 0; j < 4; j++) c[i][n][j] = 0.0f;

    uint4 pah0 = ((const uint4*)Ah)[0], pah1 = ((const uint4*)Ah)[1];
    uint4 pal0 = ((const uint4*)Al)[0], pal1 = ((const uint4*)Al)[1];
    uint4 pbh  = ((const uint4*)Bh)[0];
    uint4 pbl  = ((const uint4*)Bl)[0];

    for (int k0 = 0; k0 < K; k0 += 32) {
        __syncthreads();
        *(uint4*)&sA[0][ar * 40 + ac]     = pah0;
        *(uint4*)&sA[0][ar * 40 + ac + 8] = pah1;
        *(uint4*)&sA[1][ar * 40 + ac]     = pal0;
        *(uint4*)&sA[1][ar * 40 + ac + 8] = pal1;
        *(uint4*)&sB[0][br * 40 + bc]     = pbh;
        *(uint4*)&sB[1][br * 40 + bc]     = pbl;
        __syncthreads();
        if (k0 + 32 < K) {
            pah0 = ((const uint4*)(Ah + k0 + 32))[0];
            pah1 = ((const uint4*)(Ah + k0 + 32))[1];
            pal0 = ((const uint4*)(Al + k0 + 32))[0];
            pal1 = ((const uint4*)(Al + k0 + 32))[1];
            pbh  = ((const uint4*)(Bh + k0 + 32))[0];
            pbl  = ((const uint4*)(Bl + k0 + 32))[0];
        }
#pragma unroll
        for (int s = 0; s < 2; s++) {
            uint32_t ah[2][4], al[2][4];
#pragma unroll
            for (int i = 0; i < 2; i++) {
                const int r0 = (wm * 32 + i * 16 + g) * 40 + 16 * s + 2 * t;
                const int r1 = r0 + 8 * 40;
                ah[i][0] = *(const uint32_t*)&sA[0][r0];
                ah[i][1] = *(const uint32_t*)&sA[0][r1];
                ah[i][2] = *(const uint32_t*)&sA[0][r0 + 8];
                ah[i][3] = *(const uint32_t*)&sA[0][r1 + 8];
                al[i][0] = *(const uint32_t*)&sA[1][r0];
                al[i][1] = *(const uint32_t*)&sA[1][r1];
                al[i][2] = *(const uint32_t*)&sA[1][r0 + 8];
                al[i][3] = *(const uint32_t*)&sA[1][r1 + 8];
            }
#pragma unroll
            for (int n = 0; n < 4; n++) {
                const int ro = (wn * 32 + n * 8 + g) * 40 + 16 * s + 2 * t;
                uint32_t bh0 = *(const uint32_t*)&sB[0][ro];
                uint32_t bh1 = *(const uint32_t*)&sB[0][ro + 8];
                uint32_t bl0 = *(const uint32_t*)&sB[1][ro];
                uint32_t bl1 = *(const uint32_t*)&sB[1][ro + 8];
#pragma unroll
                for (int i = 0; i < 2; i++) {
                    mma_f16(c[i][n], ah[i], bh0, bh1);
                    mma_f16(c[i][n], ah[i], bl0, bl1);
                    mma_f16(c[i][n], al[i], bh0, bh1);
                }
            }
        }
    }

#pragma unroll
    for (int n = 0; n < 4; n++) {
        const int col = n0 + wn * 32 + n * 8 + 2 * t;
        float b0 = 0.f, b1 = 0.f;
        if (bias) { b0 = bias[col]; b1 = bias[col + 1]; }
#pragma unroll
        for (int i = 0; i < 2; i++) {
            const int row0 = m0 + wm * 32 + i * 16 + g;
            float2 v0; v0.x = c[i][n][0] + b0; v0.y = c[i][n][1] + b1;
            float2 v1; v1.x = c[i][n][2] + b0; v1.y = c[i][n][3] + b1;
            *(float2*)(Y + (size_t)row0 * Nn + col) = v0;
            *(float2*)(Y + (size_t)(row0 + 8) * Nn + col) = v1;
        }
    }
}

// ---------------------------------------------------------------------------
// Tensor-core flash attention, fixed-zero softmax reference.
// Block: 64 q-rows x 1 head, 128 threads = 4 warps (16 rows each).
// QK^T: S = q_hi.K_hi + q_lo.K_hi ; PV: O += p_hi.V_hi (V residual dropped).
// Scores (log2 domain) bounded |s| < 16 -> p = 2^s directly, no running max,
// no rescale; l accumulated per thread, reduced once at the end.
// Output written as fp16 hi/lo pair arrays (feeds proj gemm_tc directly).
// ---------------------------------------------------------------------------
__global__ __launch_bounds__(128, 3) void attn_tc(
    const float* __restrict__ qkv, const uint32_t* __restrict__ mb,
    uint16_t* __restrict__ outh, uint16_t* __restrict__ outl)
{
    __shared__ uint16_t Khi[64 * 40];
    __shared__ uint16_t Vthi[32 * 72];

    const int tid  = threadIdx.x;
    const int w    = tid >> 5;
    const int lane = tid & 31;
    const int g    = lane >> 2;
    const int t    = lane & 3;
    const int h    = blockIdx.y;
    const int q0   = blockIdx.x << 6;
    const int rA   = q0 + w * 16 + g;
    const int rB   = rA + 8;
    const float qscale = 0.17677669529663687f * 1.4426950408889634f;

    // ---- Q rows rA, rB -> A-fragments (fp16 hi + lo residual) ----
    uint32_t qhi[2][4], qlo[2][4];
    {
        const float* qpA = qkv + (size_t)rA * 768 + h * 32 + 2 * t;
        const float* qpB = qkv + (size_t)rB * 768 + h * 32 + 2 * t;
        float fA[8], fB[8];
#pragma unroll
        for (int j = 0; j < 4; j++) {
            float2 a = *(const float2*)(qpA + 8 * j);
            float2 b = *(const float2*)(qpB + 8 * j);
            fA[2 * j] = a.x * qscale; fA[2 * j + 1] = a.y * qscale;
            fB[2 * j] = b.x * qscale; fB[2 * j + 1] = b.y * qscale;
        }
#pragma unroll
        for (int s = 0; s < 2; s++) {
            splith(fA[4 * s + 0], fA[4 * s + 1], qhi[s][0], qlo[s][0]);
            splith(fB[4 * s + 0], fB[4 * s + 1], qhi[s][1], qlo[s][1]);
            splith(fA[4 * s + 2], fA[4 * s + 3], qhi[s][2], qlo[s][2]);
            splith(fB[4 * s + 2], fB[4 * s + 3], qhi[s][3], qlo[s][3]);
        }
    }

    float lA = 0.0f, lB = 0.0f;
    float o[4][4];
#pragma unroll
    for (int n = 0; n < 4; n++)
#pragma unroll
        for (int i = 0; i < 4; i++) o[n][i] = 0.0f;

    // K loader: thread owns key klr, 16-dh chunk klc
    const int klr = tid >> 1;
    const int klc = (tid & 1) * 16;
    const float* kbg = qkv + (size_t)klr * 768 + 256 + h * 32 + klc;
    // V loader: thread owns keys {2vj, 2vj+1}, 8-dh chunk vc
    const int vj = tid >> 2;
    const int vc = (tid & 3) * 8;
    const float* vbg = qkv + (size_t)(2 * vj) * 768 + 512 + h * 32 + vc;

    float4 kr[4], vr[4];
#pragma unroll
    for (int i = 0; i < 4; i++) kr[i] = ((const float4*)kbg)[i];
    vr[0] = ((const float4*)vbg)[0];
    vr[1] = ((const float4*)vbg)[1];
    vr[2] = ((const float4*)(vbg + 768))[0];
    vr[3] = ((const float4*)(vbg + 768))[1];

    for (int T = 0; T < 64; T++) {
        __syncthreads();
        // K tile (hi only)
#pragma unroll
        for (int i = 0; i < 4; i++) {
            const int base = klr * 40 + klc + 4 * i;
            *(uint32_t*)&Khi[base]     = pkh(kr[i].x, kr[i].y);
            *(uint32_t*)&Khi[base + 2] = pkh(kr[i].z, kr[i].w);
        }
        // V^T tile (hi only): 32-bit stores covering keys {2vj, 2vj+1}
        {
            float a[8] = {vr[0].x, vr[0].y, vr[0].z, vr[0].w,
                          vr[1].x, vr[1].y, vr[1].z, vr[1].w};
            float b[8] = {vr[2].x, vr[2].y, vr[2].z, vr[2].w,
                          vr[3].x, vr[3].y, vr[3].z, vr[3].w};
#pragma unroll
            for (int d = 0; d < 8; d++)
                *(uint32_t*)&Vthi[(vc + d) * 72 + 2 * vj] = pkh(a[d], b[d]);
        }
        __syncthreads();

        // prefetch next tile
        if (T < 63) {
            const size_t off = (size_t)(T + 1) * 64 * 768;
            const float4* kp = (const float4*)(kbg + off);
#pragma unroll
            for (int i = 0; i < 4; i++) kr[i] = kp[i];
            vr[0] = ((const float4*)(vbg + off))[0];
            vr[1] = ((const float4*)(vbg + off))[1];
            vr[2] = ((const float4*)(vbg + off + 768))[0];
            vr[3] = ((const float4*)(vbg + off + 768))[1];
        }

        const uint32_t wA0 = mb[(size_t)rA * 128 + 2 * T];
        const uint32_t wA1 = mb[(size_t)rA * 128 + 2 * T + 1];
        const uint32_t wB0 = mb[(size_t)rB * 128 + 2 * T];
        const uint32_t wB1 = mb[(size_t)rB * 128 + 2 * T + 1];

        // ---- S = Q.K^T : 8 n-tiles x 2 k-steps x 2 split terms ----
        float c[8][4];
#pragma unroll
        for (int n = 0; n < 8; n++)
#pragma unroll
            for (int i = 0; i < 4; i++) c[n][i] = 0.0f;

#pragma unroll
        for (int n = 0; n < 8; n++) {
            const int krow = (8 * n + g) * 40;
#pragma unroll
            for (int s = 0; s < 2; s++) {
                const int off = krow + 16 * s + 2 * t;
                uint32_t bh0 = *(const uint32_t*)&Khi[off];
                uint32_t bh1 = *(const uint32_t*)&Khi[off + 8];
                mma_f16(c[n], qhi[s], bh0, bh1);
                mma_f16(c[n], qlo[s], bh0, bh1);
            }
        }

        // ---- mask + p = 2^s (fixed-zero reference) + l accumulation ----
#pragma unroll
        for (int n = 0; n < 8; n++) {
            const int sh = (8 * n + 2 * t) & 31;
            uint32_t bA = ((n < 4) ? wA0 : wA1) >> sh;
            uint32_t bB = ((n < 4) ? wB0 : wB1) >> sh;
            c[n][0] = ex2((bA & 1u) ? c[n][0] : NEGBIG);
            c[n][1] = ex2((bA & 2u) ? c[n][1] : NEGBIG);
            c[n][2] = ex2((bB & 1u) ? c[n][2] : NEGBIG);
            c[n][3] = ex2((bB & 2u) ? c[n][3] : NEGBIG);
            lA += c[n][0] + c[n][1];
            lB += c[n][2] + c[n][3];
        }

        // ---- out += P.V : 4 k-steps x 4 dh-tiles, hi term only ----
#pragma unroll
        for (int s = 0; s < 4; s++) {
            uint32_t ph[4];
            ph[0] = pkh(c[2 * s][0],     c[2 * s][1]);
            ph[1] = pkh(c[2 * s][2],     c[2 * s][3]);
            ph[2] = pkh(c[2 * s + 1][0], c[2 * s + 1][1]);
            ph[3] = pkh(c[2 * s + 1][2], c[2 * s + 1][3]);
#pragma unroll
            for (int n = 0; n < 4; n++) {
                const int off = (8 * n + g) * 72 + 16 * s + 2 * t;
                uint32_t bh0 = *(const uint32_t*)&Vthi[off];
                uint32_t bh1 = *(const uint32_t*)&Vthi[off + 8];
                mma_f16(o[n], ph, bh0, bh1);
            }
        }
    }

    // ---- reduce l across the 4 t-threads of each row, normalize, store ----
    lA += __shfl_xor_sync(0xffffffffu, lA, 1);
    lA += __shfl_xor_sync(0xffffffffu, lA, 2);
    lB += __shfl_xor_sync(0xffffffffu, lB, 1);
    lB += __shfl_xor_sync(0xffffffffu, lB, 2);
    const float invA = 1.0f / lA;
    const float invB = 1.0f / lB;
    const int cb = h * 32 + 2 * t;
#pragma unroll
    for (int n = 0; n < 4; n++) {
        uint32_t hh, ll;
        splith(o[n][0] * invA, o[n][1] * invA, hh, ll);
        *(uint32_t*)&outh[(size_t)rA * 256 + cb + 8 * n] = hh;
        *(uint32_t*)&outl[(size_t)rA * 256 + cb + 8 * n] = ll;
        splith(o[n][2] * invB, o[n][3] * invB, hh, ll);
        *(uint32_t*)&outh[(size_t)rB * 256 + cb + 8 * n] = hh;
        *(uint32_t*)&outl[(size_t)rB * 256 + cb + 8 * n] = ll;
    }
}

// ---------------------------------------------------------------------------
extern "C" void kernel_launch(void* const* d_in, const int* in_sizes, int n_in,
                              void* d_out, int out_size)
{
    const float* x      = (const float*)d_in[0];
    const int*   adj    = (const int*)d_in[1];
    const float* w_qkv  = (const float*)d_in[2];
    const float* w_proj = (const float*)d_in[3];
    const float* b_proj = (const float*)d_in[4];
    float*       out    = (float*)d_out;

    void *pq, *pm, *pxh, *pxl, *pqh, *pql, *pph, *ppl, *pah, *pal;
    cudaGetSymbolAddress(&pq, g_qkv);
    cudaGetSymbolAddress(&pm, g_mask);
    cudaGetSymbolAddress(&pxh, g_xhi);  cudaGetSymbolAddress(&pxl, g_xlo);
    cudaGetSymbolAddress(&pqh, g_wqh);  cudaGetSymbolAddress(&pql, g_wql);
    cudaGetSymbolAddress(&pph, g_wph);  cudaGetSymbolAddress(&ppl, g_wpl);
    cudaGetSymbolAddress(&pah, g_ath);  cudaGetSymbolAddress(&pal, g_atl);

    float*    qkv = (float*)pq;
    uint32_t* msk = (uint32_t*)pm;
    uint16_t* xhi = (uint16_t*)pxh; uint16_t* xlo = (uint16_t*)pxl;
    uint16_t* wqh = (uint16_t*)pqh; uint16_t* wql = (uint16_t*)pql;
    uint16_t* wph = (uint16_t*)pph; uint16_t* wpl = (uint16_t*)ppl;
    uint16_t* ath = (uint16_t*)pah; uint16_t* atl = (uint16_t*)pal;

    // 0) packs
    pack_mask<<<(NTOK * (NTOK / 32)) / 256, 256>>>(adj, msk);
    pack_halves<<<(NTOK * CDIM / 4) / 256, 256>>>(x, xhi, xlo);
    pack_halves<<<(3 * CDIM * CDIM / 4) / 256, 256>>>(w_qkv, wqh, wql);
    pack_halves<<<(CDIM * CDIM / 4) / 256, 256>>>(w_proj, wph, wpl);

    // 1) QKV projection (tensor cores): qkv[4096,768] = x @ w_qkv^T
    {
        dim3 grid(768 / 64, NTOK / 128);
        gemm_tc<<<grid, 256>>>(xhi, xlo, wqh, wql, nullptr, qkv,
                               NTOK, 3 * CDIM, CDIM);
    }
    // 2) tensor-core masked flash attention -> fp16 hi/lo output
    {
        dim3 grid(NTOK / 64, HEADS);
        attn_tc<<<grid, 128>>>(qkv, msk, ath, atl);
    }
    // 3) output projection + bias (tensor cores)
    {
        dim3 grid(CDIM / 64, NTOK / 128);
        gemm_tc<<<grid, 256>>>(ath, atl, wph, wpl, b_proj, out,
                               NTOK, CDIM, CDIM);
    }
}

// round 9
// speedup vs baseline: 7.0701x; 1.1642x over previous
#include <cuda_runtime.h>
#include <cuda_fp16.h>
#include <cstdint>

#define NTOK 4096
#define CDIM 256
#define HEADS 8
#define NEGBIG (-1.0e30f)
#define QSCALE (0.17677669529663687f * 1.4426950408889634f)

// scratch (allocation-free rule: device globals)
__device__ uint32_t g_mask[NTOK * (NTOK / 32)];    // packed adj bitmask, 2 MB
__device__ uint16_t g_xhi[NTOK * CDIM],  g_xlo[NTOK * CDIM];        // x split
__device__ uint16_t g_wqh[3 * CDIM * CDIM], g_wql[3 * CDIM * CDIM]; // w_qkv split
__device__ uint16_t g_wph[CDIM * CDIM],  g_wpl[CDIM * CDIM];        // w_proj split
__device__ uint16_t g_kvh[NTOK * 3 * CDIM];        // qkv fp16 (q pre-scaled)
__device__ uint16_t g_ath[NTOK * CDIM],  g_atl[NTOK * CDIM];        // attn out split

// ---------------------------------------------------------------------------
// helpers
// ---------------------------------------------------------------------------
__device__ __forceinline__ float ex2(float x) {
    float y;
    asm("ex2.approx.ftz.f32 %0, %1;" : "=f"(y) : "f"(x));
    return y;
}
__device__ __forceinline__ uint32_t pkh(float x, float y) {  // f16x2(lo=x,hi=y)
    uint32_t r;
    asm("cvt.rn.f16x2.f32 %0, %1, %2;" : "=r"(r) : "f"(y), "f"(x));
    return r;
}
__device__ __forceinline__ void splith(float x, float y, uint32_t& hi, uint32_t& lo) {
    uint32_t h = pkh(x, y);
    float xh, yh;
    asm("{ .reg .f16 a,b;\n  mov.b32 {a,b}, %2;\n  cvt.f32.f16 %0, a;\n  cvt.f32.f16 %1, b; }"
        : "=f"(xh), "=f"(yh) : "r"(h));
    hi = h;
    lo = pkh(x - xh, y - yh);
}
__device__ __forceinline__ uint32_t prmt(uint32_t a, uint32_t b, uint32_t sel) {
    uint32_t r;
    asm("prmt.b32 %0, %1, %2, %3;" : "=r"(r) : "r"(a), "r"(b), "r"(sel));
    return r;
}
// m16n8k16 fp16 MMA, f32 accumulate (A row-major, B col-major)
__device__ __forceinline__ void mma_f16(float* c, const uint32_t* a,
                                        uint32_t b0, uint32_t b1) {
    asm volatile(
        "mma.sync.aligned.m16n8k16.row.col.f32.f16.f16.f32 "
        "{%0,%1,%2,%3}, {%4,%5,%6,%7}, {%8,%9}, {%0,%1,%2,%3};"
        : "+f"(c[0]), "+f"(c[1]), "+f"(c[2]), "+f"(c[3])
        : "r"(a[0]), "r"(a[1]), "r"(a[2]), "r"(a[3]), "r"(b0), "r"(b1));
}

// ---------------------------------------------------------------------------
// pack adj into bitmask
// ---------------------------------------------------------------------------
__global__ __launch_bounds__(256) void pack_mask(
    const int* __restrict__ adj, uint32_t* __restrict__ mb)
{
    int w = blockIdx.x * blockDim.x + threadIdx.x;
    const int4* p = (const int4*)(adj + (size_t)w * 32);
    uint32_t bits = 0;
#pragma unroll
    for (int i = 0; i < 8; i++) {
        int4 a = p[i];
        bits |= (a.x > 0 ? 1u : 0u) << (4 * i + 0);
        bits |= (a.y > 0 ? 1u : 0u) << (4 * i + 1);
        bits |= (a.z > 0 ? 1u : 0u) << (4 * i + 2);
        bits |= (a.w > 0 ? 1u : 0u) << (4 * i + 3);
    }
    mb[w] = bits;
}

// ---------------------------------------------------------------------------
// pack f32 -> fp16 hi + fp16 lo residual (4 floats per thread)
// ---------------------------------------------------------------------------
__global__ __launch_bounds__(256) void pack_halves(
    const float* __restrict__ src, uint16_t* __restrict__ hi,
    uint16_t* __restrict__ lo)
{
    int i = blockIdx.x * blockDim.x + threadIdx.x;
    float4 f = ((const float4*)src)[i];
    uint32_t h01, l01, h23, l23;
    splith(f.x, f.y, h01, l01);
    splith(f.z, f.w, h23, l23);
    ((uint2*)hi)[i] = make_uint2(h01, h23);
    ((uint2*)lo)[i] = make_uint2(l01, l23);
}

// ---------------------------------------------------------------------------
// Split-fp16 tensor-core GEMM core (3 terms). Block tile 128x64, 256 threads,
// warp tile 32x32, BK=32. Two epilogues:
//   gemm_tc  : f32 output + bias (final projection)
//   gemm_tch : fp16 hi-only output, per-column-block scale (QKV production)
// ---------------------------------------------------------------------------
#define GEMM_BODY                                                              \
    __shared__ uint16_t sA[2][128 * 40];                                       \
    __shared__ uint16_t sB[2][64 * 40];                                        \
    const int tid = threadIdx.x;                                               \
    const int w    = tid >> 5;                                                 \
    const int lane = tid & 31;                                                 \
    const int g    = lane >> 2;                                                \
    const int t    = lane & 3;                                                 \
    const int wm   = w >> 1;                                                   \
    const int wn   = w & 1;                                                    \
    const int m0 = blockIdx.y << 7;                                            \
    const int n0 = blockIdx.x << 6;                                            \
    const int ar = tid >> 1, ac = (tid & 1) * 16;                              \
    const int br = tid >> 2, bc = (tid & 3) * 8;                               \
    const uint16_t* Ah = Ahi + (size_t)(m0 + ar) * K + ac;                     \
    const uint16_t* Al = Alo + (size_t)(m0 + ar) * K + ac;                     \
    const uint16_t* Bh = Bhi + (size_t)(n0 + br) * K + bc;                     \
    const uint16_t* Bl = Blo + (size_t)(n0 + br) * K + bc;                     \
    float c[2][4][4];                                                          \
    _Pragma("unroll")                                                          \
    for (int i = 0; i < 2; i++)                                                \
        _Pragma("unroll")                                                      \
        for (int n = 0; n < 4; n++)                                            \
            _Pragma("unroll")                                                  \
            for (int j = 0; j < 4; j++) c[i][n][j] = 0.0f;                     \
    uint4 pah0 = ((const uint4*)Ah)[0], pah1 = ((const uint4*)Ah)[1];          \
    uint4 pal0 = ((const uint4*)Al)[0], pal1 = ((const uint4*)Al)[1];          \
    uint4 pbh  = ((const uint4*)Bh)[0];                                        \
    uint4 pbl  = ((const uint4*)Bl)[0];                                        \
    for (int k0 = 0; k0 < K; k0 += 32) {                                       \
        __syncthreads();                                                       \
        *(uint4*)&sA[0][ar * 40 + ac]     = pah0;                              \
        *(uint4*)&sA[0][ar * 40 + ac + 8] = pah1;                              \
        *(uint4*)&sA[1][ar * 40 + ac]     = pal0;                              \
        *(uint4*)&sA[1][ar * 40 + ac + 8] = pal1;                              \
        *(uint4*)&sB[0][br * 40 + bc]     = pbh;                               \
        *(uint4*)&sB[1][br * 40 + bc]     = pbl;                               \
        __syncthreads();                                                       \
        if (k0 + 32 < K) {                                                     \
            pah0 = ((const uint4*)(Ah + k0 + 32))[0];                          \
            pah1 = ((const uint4*)(Ah + k0 + 32))[1];                          \
            pal0 = ((const uint4*)(Al + k0 + 32))[0];                          \
            pal1 = ((const uint4*)(Al + k0 + 32))[1];                          \
            pbh  = ((const uint4*)(Bh + k0 + 32))[0];                          \
            pbl  = ((const uint4*)(Bl + k0 + 32))[0];                          \
        }                                                                      \
        _Pragma("unroll")                                                      \
        for (int s = 0; s < 2; s++) {                                          \
            uint32_t ah[2][4], al[2][4];                                       \
            _Pragma("unroll")                                                  \
            for (int i = 0; i < 2; i++) {                                      \
                const int r0 = (wm * 32 + i * 16 + g) * 40 + 16 * s + 2 * t;   \
                const int r1 = r0 + 8 * 40;                                    \
                ah[i][0] = *(const uint32_t*)&sA[0][r0];                       \
                ah[i][1] = *(const uint32_t*)&sA[0][r1];                       \
                ah[i][2] = *(const uint32_t*)&sA[0][r0 + 8];                   \
                ah[i][3] = *(const uint32_t*)&sA[0][r1 + 8];                   \
                al[i][0] = *(const uint32_t*)&sA[1][r0];                       \
                al[i][1] = *(const uint32_t*)&sA[1][r1];                       \
                al[i][2] = *(const uint32_t*)&sA[1][r0 + 8];                   \
                al[i][3] = *(const uint32_t*)&sA[1][r1 + 8];                   \
            }                                                                  \
            _Pragma("unroll")                                                  \
            for (int n = 0; n < 4; n++) {                                      \
                const int ro = (wn * 32 + n * 8 + g) * 40 + 16 * s + 2 * t;    \
                uint32_t bh0 = *(const uint32_t*)&sB[0][ro];                   \
                uint32_t bh1 = *(const uint32_t*)&sB[0][ro + 8];               \
                uint32_t bl0 = *(const uint32_t*)&sB[1][ro];                   \
                uint32_t bl1 = *(const uint32_t*)&sB[1][ro + 8];               \
                _Pragma("unroll")                                              \
                for (int i = 0; i < 2; i++) {                                  \
                    mma_f16(c[i][n], ah[i], bh0, bh1);                         \
                    mma_f16(c[i][n], ah[i], bl0, bl1);                         \
                    mma_f16(c[i][n], al[i], bh0, bh1);                         \
                }                                                              \
            }                                                                  \
        }                                                                      \
    }

__global__ __launch_bounds__(256) void gemm_tc(
    const uint16_t* __restrict__ Ahi, const uint16_t* __restrict__ Alo,
    const uint16_t* __restrict__ Bhi, const uint16_t* __restrict__ Blo,
    const float* __restrict__ bias, float* __restrict__ Y,
    int M, int Nn, int K)
{
    GEMM_BODY
#pragma unroll
    for (int n = 0; n < 4; n++) {
        const int col = n0 + wn * 32 + n * 8 + 2 * t;
        float b0 = 0.f, b1 = 0.f;
        if (bias) { b0 = bias[col]; b1 = bias[col + 1]; }
#pragma unroll
        for (int i = 0; i < 2; i++) {
            const int row0 = m0 + wm * 32 + i * 16 + g;
            float2 v0; v0.x = c[i][n][0] + b0; v0.y = c[i][n][1] + b1;
            float2 v1; v1.x = c[i][n][2] + b0; v1.y = c[i][n][3] + b1;
            *(float2*)(Y + (size_t)row0 * Nn + col) = v0;
            *(float2*)(Y + (size_t)(row0 + 8) * Nn + col) = v1;
        }
    }
}

// hi-only fp16 output; q columns (col < 256) scaled by QSCALE
__global__ __launch_bounds__(256) void gemm_tch(
    const uint16_t* __restrict__ Ahi, const uint16_t* __restrict__ Alo,
    const uint16_t* __restrict__ Bhi, const uint16_t* __restrict__ Blo,
    uint16_t* __restrict__ Yh, int M, int Nn, int K)
{
    GEMM_BODY
    const float sc = (n0 < 256) ? QSCALE : 1.0f;
#pragma unroll
    for (int n = 0; n < 4; n++) {
        const int col = n0 + wn * 32 + n * 8 + 2 * t;
#pragma unroll
        for (int i = 0; i < 2; i++) {
            const int row0 = m0 + wm * 32 + i * 16 + g;
            *(uint32_t*)&Yh[(size_t)row0 * Nn + col] =
                pkh(c[i][n][0] * sc, c[i][n][1] * sc);
            *(uint32_t*)&Yh[(size_t)(row0 + 8) * Nn + col] =
                pkh(c[i][n][2] * sc, c[i][n][3] * sc);
        }
    }
}

// ---------------------------------------------------------------------------
// Tensor-core flash attention, pure fp16 operands, fixed-zero softmax ref.
// Block: 64 q-rows x 1 head, 128 threads = 4 warps.
// qkv is already fp16 (q pre-scaled by QSCALE at the GEMM epilogue), so the
// mainloop does NO float->half conversion: K tile is a raw smem copy, V^T is
// built with PRMT, Q fragments are direct 32-bit loads.
// ---------------------------------------------------------------------------
__global__ __launch_bounds__(128, 3) void attn_tc(
    const uint16_t* __restrict__ qkv, const uint32_t* __restrict__ mb,
    uint16_t* __restrict__ outh, uint16_t* __restrict__ outl)
{
    __shared__ __align__(16) uint16_t Khi[64 * 40];
    __shared__ __align__(16) uint16_t Vthi[32 * 72];

    const int tid  = threadIdx.x;
    const int w    = tid >> 5;
    const int lane = tid & 31;
    const int g    = lane >> 2;
    const int t    = lane & 3;
    const int h    = blockIdx.y;
    const int q0   = blockIdx.x << 6;
    const int rA   = q0 + w * 16 + g;
    const int rB   = rA + 8;

    // ---- Q fragments: direct packed loads (scale already folded) ----
    uint32_t qa[2][4];
#pragma unroll
    for (int s = 0; s < 2; s++) {
        const size_t bA = (size_t)rA * 768 + h * 32 + 16 * s + 2 * t;
        const size_t bB = (size_t)rB * 768 + h * 32 + 16 * s + 2 * t;
        qa[s][0] = *(const uint32_t*)&qkv[bA];
        qa[s][1] = *(const uint32_t*)&qkv[bB];
        qa[s][2] = *(const uint32_t*)&qkv[bA + 8];
        qa[s][3] = *(const uint32_t*)&qkv[bB + 8];
    }

    float lA = 0.0f, lB = 0.0f;
    float o[4][4];
#pragma unroll
    for (int n = 0; n < 4; n++)
#pragma unroll
        for (int i = 0; i < 4; i++) o[n][i] = 0.0f;

    // K loader: thread owns key klr, 16-half chunk klc
    const int klr = tid >> 1;
    const int klc = (tid & 1) * 16;
    const uint16_t* kbg = qkv + (size_t)klr * 768 + 256 + h * 32 + klc;
    // V loader: thread owns keys {2vj, 2vj+1}, 8-half chunk vc
    const int vj = tid >> 2;
    const int vc = (tid & 3) * 8;
    const uint16_t* vbg = qkv + (size_t)(2 * vj) * 768 + 512 + h * 32 + vc;

    uint4 kr0, kr1, va, vb;
    kr0 = ((const uint4*)kbg)[0];
    kr1 = ((const uint4*)kbg)[1];
    va  = *(const uint4*)vbg;
    vb  = *(const uint4*)(vbg + 768);

    for (int T = 0; T < 64; T++) {
        __syncthreads();
        // K tile: raw copy
        *(uint4*)&Khi[klr * 40 + klc]     = kr0;
        *(uint4*)&Khi[klr * 40 + klc + 8] = kr1;
        // V^T tile: PRMT-interleave keys 2vj / 2vj+1 per dh
        {
            const uint32_t aw[4] = {va.x, va.y, va.z, va.w};
            const uint32_t bw[4] = {vb.x, vb.y, vb.z, vb.w};
#pragma unroll
            for (int d = 0; d < 8; d++) {
                uint32_t x = prmt(aw[d >> 1], bw[d >> 1],
                                  (d & 1) ? 0x7632u : 0x5410u);
                *(uint32_t*)&Vthi[(vc + d) * 72 + 2 * vj] = x;
            }
        }
        __syncthreads();

        // prefetch next tile
        if (T < 63) {
            const size_t off = (size_t)(T + 1) * 64 * 768;
            kr0 = ((const uint4*)(kbg + off))[0];
            kr1 = ((const uint4*)(kbg + off))[1];
            va  = *(const uint4*)(vbg + off);
            vb  = *(const uint4*)(vbg + off + 768);
        }

        const uint32_t wA0 = mb[(size_t)rA * 128 + 2 * T];
        const uint32_t wA1 = mb[(size_t)rA * 128 + 2 * T + 1];
        const uint32_t wB0 = mb[(size_t)rB * 128 + 2 * T];
        const uint32_t wB1 = mb[(size_t)rB * 128 + 2 * T + 1];

        // ---- S = Q.K^T : 8 n-tiles x 2 k-steps, single fp16 term ----
        float c[8][4];
#pragma unroll
        for (int n = 0; n < 8; n++)
#pragma unroll
            for (int i = 0; i < 4; i++) c[n][i] = 0.0f;

#pragma unroll
        for (int n = 0; n < 8; n++) {
            const int krow = (8 * n + g) * 40;
#pragma unroll
            for (int s = 0; s < 2; s++) {
                const int off = krow + 16 * s + 2 * t;
                uint32_t bh0 = *(const uint32_t*)&Khi[off];
                uint32_t bh1 = *(const uint32_t*)&Khi[off + 8];
                mma_f16(c[n], qa[s], bh0, bh1);
            }
        }

        // ---- mask + p = 2^s + l accumulation ----
#pragma unroll
        for (int n = 0; n < 8; n++) {
            const int sh = (8 * n + 2 * t) & 31;
            uint32_t bA = ((n < 4) ? wA0 : wA1) >> sh;
            uint32_t bB = ((n < 4) ? wB0 : wB1) >> sh;
            c[n][0] = ex2((bA & 1u) ? c[n][0] : NEGBIG);
            c[n][1] = ex2((bA & 2u) ? c[n][1] : NEGBIG);
            c[n][2] = ex2((bB & 1u) ? c[n][2] : NEGBIG);
            c[n][3] = ex2((bB & 2u) ? c[n][3] : NEGBIG);
            lA += c[n][0] + c[n][1];
            lB += c[n][2] + c[n][3];
        }

        // ---- out += P.V : 4 k-steps x 4 dh-tiles ----
#pragma unroll
        for (int s = 0; s < 4; s++) {
            uint32_t ph[4];
            ph[0] = pkh(c[2 * s][0],     c[2 * s][1]);
            ph[1] = pkh(c[2 * s][2],     c[2 * s][3]);
            ph[2] = pkh(c[2 * s + 1][0], c[2 * s + 1][1]);
            ph[3] = pkh(c[2 * s + 1][2], c[2 * s + 1][3]);
#pragma unroll
            for (int n = 0; n < 4; n++) {
                const int off = (8 * n + g) * 72 + 16 * s + 2 * t;
                uint32_t bh0 = *(const uint32_t*)&Vthi[off];
                uint32_t bh1 = *(const uint32_t*)&Vthi[off + 8];
                mma_f16(o[n], ph, bh0, bh1);
            }
        }
    }

    // ---- reduce l across the 4 t-threads of each row, normalize, store ----
    lA += __shfl_xor_sync(0xffffffffu, lA, 1);
    lA += __shfl_xor_sync(0xffffffffu, lA, 2);
    lB += __shfl_xor_sync(0xffffffffu, lB, 1);
    lB += __shfl_xor_sync(0xffffffffu, lB, 2);
    const float invA = 1.0f / lA;
    const float invB = 1.0f / lB;
    const int cb = h * 32 + 2 * t;
#pragma unroll
    for (int n = 0; n < 4; n++) {
        uint32_t hh, ll;
        splith(o[n][0] * invA, o[n][1] * invA, hh, ll);
        *(uint32_t*)&outh[(size_t)rA * 256 + cb + 8 * n] = hh;
        *(uint32_t*)&outl[(size_t)rA * 256 + cb + 8 * n] = ll;
        splith(o[n][2] * invB, o[n][3] * invB, hh, ll);
        *(uint32_t*)&outh[(size_t)rB * 256 + cb + 8 * n] = hh;
        *(uint32_t*)&outl[(size_t)rB * 256 + cb + 8 * n] = ll;
    }
}

// ---------------------------------------------------------------------------
extern "C" void kernel_launch(void* const* d_in, const int* in_sizes, int n_in,
                              void* d_out, int out_size)
{
    const float* x      = (const float*)d_in[0];
    const int*   adj    = (const int*)d_in[1];
    const float* w_qkv  = (const float*)d_in[2];
    const float* w_proj = (const float*)d_in[3];
    const float* b_proj = (const float*)d_in[4];
    float*       out    = (float*)d_out;

    void *pm, *pxh, *pxl, *pqh, *pql, *pph, *ppl, *pkv, *pah, *pal;
    cudaGetSymbolAddress(&pm, g_mask);
    cudaGetSymbolAddress(&pxh, g_xhi);  cudaGetSymbolAddress(&pxl, g_xlo);
    cudaGetSymbolAddress(&pqh, g_wqh);  cudaGetSymbolAddress(&pql, g_wql);
    cudaGetSymbolAddress(&pph, g_wph);  cudaGetSymbolAddress(&ppl, g_wpl);
    cudaGetSymbolAddress(&pkv, g_kvh);
    cudaGetSymbolAddress(&pah, g_ath);  cudaGetSymbolAddress(&pal, g_atl);

    uint32_t* msk = (uint32_t*)pm;
    uint16_t* xhi = (uint16_t*)pxh; uint16_t* xlo = (uint16_t*)pxl;
    uint16_t* wqh = (uint16_t*)pqh; uint16_t* wql = (uint16_t*)pql;
    uint16_t* wph = (uint16_t*)pph; uint16_t* wpl = (uint16_t*)ppl;
    uint16_t* kvh = (uint16_t*)pkv;
    uint16_t* ath = (uint16_t*)pah; uint16_t* atl = (uint16_t*)pal;

    // 0) packs
    pack_mask<<<(NTOK * (NTOK / 32)) / 256, 256>>>(adj, msk);
    pack_halves<<<(NTOK * CDIM / 4) / 256, 256>>>(x, xhi, xlo);
    pack_halves<<<(3 * CDIM * CDIM / 4) / 256, 256>>>(w_qkv, wqh, wql);
    pack_halves<<<(CDIM * CDIM / 4) / 256, 256>>>(w_proj, wph, wpl);

    // 1) QKV projection -> fp16 (q columns pre-scaled)
    {
        dim3 grid(768 / 64, NTOK / 128);
        gemm_tch<<<grid, 256>>>(xhi, xlo, wqh, wql, kvh, NTOK, 3 * CDIM, CDIM);
    }
    // 2) tensor-core masked flash attention -> fp16 hi/lo output
    {
        dim3 grid(NTOK / 64, HEADS);
        attn_tc<<<grid, 128>>>(kvh, msk, ath, atl);
    }
    // 3) output projection + bias (f32 out)
    {
        dim3 grid(CDIM / 64, NTOK / 128);
        gemm_tc<<<grid, 256>>>(ath, atl, wph, wpl, b_proj, out,
                               NTOK, CDIM, CDIM);
    }
}

// round 11
// speedup vs baseline: 7.5861x; 1.0730x over previous
#include <cuda_runtime.h>
#include <cuda_fp16.h>
#include <cstdint>

#define NTOK 4096
#define CDIM 256
#define HEADS 8
#define NEGBIG (-1.0e30f)
#define QSCALE (0.17677669529663687f * 1.4426950408889634f)

// scratch (allocation-free rule: device globals)
__device__ uint32_t g_mask[NTOK * (NTOK / 32)];    // packed adj bitmask, 2 MB
__device__ uint16_t g_xhi[NTOK * CDIM],  g_xlo[NTOK * CDIM];        // x split
__device__ uint16_t g_wqh[3 * CDIM * CDIM], g_wql[3 * CDIM * CDIM]; // w_qkv split
__device__ uint16_t g_wph[CDIM * CDIM],  g_wpl[CDIM * CDIM];        // w_proj split
__device__ uint16_t g_kvh[NTOK * 3 * CDIM];        // qkv fp16 (q pre-scaled)
__device__ uint16_t g_ath[NTOK * CDIM],  g_atl[NTOK * CDIM];        // attn out split

// ---------------------------------------------------------------------------
// helpers
// ---------------------------------------------------------------------------
__device__ __forceinline__ float ex2(float x) {
    float y;
    asm("ex2.approx.ftz.f32 %0, %1;" : "=f"(y) : "f"(x));
    return y;
}
__device__ __forceinline__ uint32_t pkh(float x, float y) {  // f16x2(lo=x,hi=y)
    uint32_t r;
    asm("cvt.rn.f16x2.f32 %0, %1, %2;" : "=r"(r) : "f"(y), "f"(x));
    return r;
}
__device__ __forceinline__ void splith(float x, float y, uint32_t& hi, uint32_t& lo) {
    uint32_t h = pkh(x, y);
    float xh, yh;
    asm("{ .reg .f16 a,b;\n  mov.b32 {a,b}, %2;\n  cvt.f32.f16 %0, a;\n  cvt.f32.f16 %1, b; }"
        : "=f"(xh), "=f"(yh) : "r"(h));
    hi = h;
    lo = pkh(x - xh, y - yh);
}
__device__ __forceinline__ uint32_t prmt(uint32_t a, uint32_t b, uint32_t sel) {
    uint32_t r;
    asm("prmt.b32 %0, %1, %2, %3;" : "=r"(r) : "r"(a), "r"(b), "r"(sel));
    return r;
}
__device__ __forceinline__ uint32_t smem_u32(const void* p) {
    uint32_t a;
    asm("{ .reg .u64 t; cvta.to.shared.u64 t, %1; cvt.u32.u64 %0, t; }" : "=r"(a) : "l"(p));
    return a;
}
// m16n8k16 fp16 MMA, f32 accumulate (A row-major, B col-major)
__device__ __forceinline__ void mma_f16(float* c, const uint32_t* a,
                                        uint32_t b0, uint32_t b1) {
    asm volatile(
        "mma.sync.aligned.m16n8k16.row.col.f32.f16.f16.f32 "
        "{%0,%1,%2,%3}, {%4,%5,%6,%7}, {%8,%9}, {%0,%1,%2,%3};"
        : "+f"(c[0]), "+f"(c[1]), "+f"(c[2]), "+f"(c[3])
        : "r"(a[0]), "r"(a[1]), "r"(a[2]), "r"(a[3]), "r"(b0), "r"(b1));
}
// ldmatrix x4: four 8x8 b16 matrices, per-lane row addresses
__device__ __forceinline__ void ldsm4(uint32_t* r, uint32_t a) {
    asm volatile("ldmatrix.sync.aligned.m8n8.x4.shared.b16 {%0,%1,%2,%3}, [%4];"
        : "=r"(r[0]), "=r"(r[1]), "=r"(r[2]), "=r"(r[3]) : "r"(a));
}

// ---------------------------------------------------------------------------
// pack adj into bitmask
// ---------------------------------------------------------------------------
__global__ __launch_bounds__(256) void pack_mask(
    const int* __restrict__ adj, uint32_t* __restrict__ mb)
{
    int w = blockIdx.x * blockDim.x + threadIdx.x;
    const int4* p = (const int4*)(adj + (size_t)w * 32);
    uint32_t bits = 0;
#pragma unroll
    for (int i = 0; i < 8; i++) {
        int4 a = p[i];
        bits |= (a.x > 0 ? 1u : 0u) << (4 * i + 0);
        bits |= (a.y > 0 ? 1u : 0u) << (4 * i + 1);
        bits |= (a.z > 0 ? 1u : 0u) << (4 * i + 2);
        bits |= (a.w > 0 ? 1u : 0u) << (4 * i + 3);
    }
    mb[w] = bits;
}

// ---------------------------------------------------------------------------
// pack f32 -> fp16 hi + fp16 lo residual (4 floats per thread)
// ---------------------------------------------------------------------------
__global__ __launch_bounds__(256) void pack_halves(
    const float* __restrict__ src, uint16_t* __restrict__ hi,
    uint16_t* __restrict__ lo)
{
    int i = blockIdx.x * blockDim.x + threadIdx.x;
    float4 f = ((const float4*)src)[i];
    uint32_t h01, l01, h23, l23;
    splith(f.x, f.y, h01, l01);
    splith(f.z, f.w, h23, l23);
    ((uint2*)hi)[i] = make_uint2(h01, h23);
    ((uint2*)lo)[i] = make_uint2(l01, l23);
}

// ---------------------------------------------------------------------------
// Split-fp16 tensor-core GEMM core (3 terms). Block tile 128x64, 256 threads,
// warp tile 32x32, BK=32.
// ---------------------------------------------------------------------------
#define GEMM_BODY                                                              \
    __shared__ uint16_t sA[2][128 * 40];                                       \
    __shared__ uint16_t sB[2][64 * 40];                                        \
    const int tid = threadIdx.x;                                               \
    const int w    = tid >> 5;                                                 \
    const int lane = tid & 31;                                                 \
    const int g    = lane >> 2;                                                \
    const int t    = lane & 3;                                                 \
    const int wm   = w >> 1;                                                   \
    const int wn   = w & 1;                                                    \
    const int m0 = blockIdx.y << 7;                                            \
    const int n0 = blockIdx.x << 6;                                            \
    const int ar = tid >> 1, ac = (tid & 1) * 16;                              \
    const int br = tid >> 2, bc = (tid & 3) * 8;                               \
    const uint16_t* Ah = Ahi + (size_t)(m0 + ar) * K + ac;                     \
    const uint16_t* Al = Alo + (size_t)(m0 + ar) * K + ac;                     \
    const uint16_t* Bh = Bhi + (size_t)(n0 + br) * K + bc;                     \
    const uint16_t* Bl = Blo + (size_t)(n0 + br) * K + bc;                     \
    float c[2][4][4];                                                          \
    _Pragma("unroll")                                                          \
    for (int i = 0; i < 2; i++)                                                \
        _Pragma("unroll")                                                      \
        for (int n = 0; n < 4; n++)                                            \
            _Pragma("unroll")                                                  \
            for (int j = 0; j < 4; j++) c[i][n][j] = 0.0f;                     \
    uint4 pah0 = ((const uint4*)Ah)[0], pah1 = ((const uint4*)Ah)[1];          \
    uint4 pal0 = ((const uint4*)Al)[0], pal1 = ((const uint4*)Al)[1];          \
    uint4 pbh  = ((const uint4*)Bh)[0];                                        \
    uint4 pbl  = ((const uint4*)Bl)[0];                                        \
    for (int k0 = 0; k0 < K; k0 += 32) {                                       \
        __syncthreads();                                                       \
        *(uint4*)&sA[0][ar * 40 + ac]     = pah0;                              \
        *(uint4*)&sA[0][ar * 40 + ac + 8] = pah1;                              \
        *(uint4*)&sA[1][ar * 40 + ac]     = pal0;                              \
        *(uint4*)&sA[1][ar * 40 + ac + 8] = pal1;                              \
        *(uint4*)&sB[0][br * 40 + bc]     = pbh;                               \
        *(uint4*)&sB[1][br * 40 + bc]     = pbl;                               \
        __syncthreads();                                                       \
        if (k0 + 32 < K) {                                                     \
            pah0 = ((const uint4*)(Ah + k0 + 32))[0];                          \
            pah1 = ((const uint4*)(Ah + k0 + 32))[1];                          \
            pal0 = ((const uint4*)(Al + k0 + 32))[0];                          \
            pal1 = ((const uint4*)(Al + k0 + 32))[1];                          \
            pbh  = ((const uint4*)(Bh + k0 + 32))[0];                          \
            pbl  = ((const uint4*)(Bl + k0 + 32))[0];                          \
        }                                                                      \
        _Pragma("unroll")                                                      \
        for (int s = 0; s < 2; s++) {                                          \
            uint32_t ah[2][4], al[2][4];                                       \
            _Pragma("unroll")                                                  \
            for (int i = 0; i < 2; i++) {                                      \
                const int r0 = (wm * 32 + i * 16 + g) * 40 + 16 * s + 2 * t;   \
                const int r1 = r0 + 8 * 40;                                    \
                ah[i][0] = *(const uint32_t*)&sA[0][r0];                       \
                ah[i][1] = *(const uint32_t*)&sA[0][r1];                       \
                ah[i][2] = *(const uint32_t*)&sA[0][r0 + 8];                   \
                ah[i][3] = *(const uint32_t*)&sA[0][r1 + 8];                   \
                al[i][0] = *(const uint32_t*)&sA[1][r0];                       \
                al[i][1] = *(const uint32_t*)&sA[1][r1];                       \
                al[i][2] = *(const uint32_t*)&sA[1][r0 + 8];                   \
                al[i][3] = *(const uint32_t*)&sA[1][r1 + 8];                   \
            }                                                                  \
            _Pragma("unroll")                                                  \
            for (int n = 0; n < 4; n++) {                                      \
                const int ro = (wn * 32 + n * 8 + g) * 40 + 16 * s + 2 * t;    \
                uint32_t bh0 = *(const uint32_t*)&sB[0][ro];                   \
                uint32_t bh1 = *(const uint32_t*)&sB[0][ro + 8];               \
                uint32_t bl0 = *(const uint32_t*)&sB[1][ro];                   \
                uint32_t bl1 = *(const uint32_t*)&sB[1][ro + 8];               \
                _Pragma("unroll")                                              \
                for (int i = 0; i < 2; i++) {                                  \
                    mma_f16(c[i][n], ah[i], bh0, bh1);                         \
                    mma_f16(c[i][n], ah[i], bl0, bl1);                         \
                    mma_f16(c[i][n], al[i], bh0, bh1);                         \
                }                                                              \
            }                                                                  \
        }                                                                      \
    }

__global__ __launch_bounds__(256) void gemm_tc(
    const uint16_t* __restrict__ Ahi, const uint16_t* __restrict__ Alo,
    const uint16_t* __restrict__ Bhi, const uint16_t* __restrict__ Blo,
    const float* __restrict__ bias, float* __restrict__ Y,
    int M, int Nn, int K)
{
    GEMM_BODY
#pragma unroll
    for (int n = 0; n < 4; n++) {
        const int col = n0 + wn * 32 + n * 8 + 2 * t;
        float b0 = 0.f, b1 = 0.f;
        if (bias) { b0 = bias[col]; b1 = bias[col + 1]; }
#pragma unroll
        for (int i = 0; i < 2; i++) {
            const int row0 = m0 + wm * 32 + i * 16 + g;
            float2 v0; v0.x = c[i][n][0] + b0; v0.y = c[i][n][1] + b1;
            float2 v1; v1.x = c[i][n][2] + b0; v1.y = c[i][n][3] + b1;
            *(float2*)(Y + (size_t)row0 * Nn + col) = v0;
            *(float2*)(Y + (size_t)(row0 + 8) * Nn + col) = v1;
        }
    }
}

// hi-only fp16 output; q columns (col < 256) scaled by QSCALE
__global__ __launch_bounds__(256) void gemm_tch(
    const uint16_t* __restrict__ Ahi, const uint16_t* __restrict__ Alo,
    const uint16_t* __restrict__ Bhi, const uint16_t* __restrict__ Blo,
    uint16_t* __restrict__ Yh, int M, int Nn, int K)
{
    GEMM_BODY
    const float sc = (n0 < 256) ? QSCALE : 1.0f;
#pragma unroll
    for (int n = 0; n < 4; n++) {
        const int col = n0 + wn * 32 + n * 8 + 2 * t;
#pragma unroll
        for (int i = 0; i < 2; i++) {
            const int row0 = m0 + wm * 32 + i * 16 + g;
            *(uint32_t*)&Yh[(size_t)row0 * Nn + col] =
                pkh(c[i][n][0] * sc, c[i][n][1] * sc);
            *(uint32_t*)&Yh[(size_t)(row0 + 8) * Nn + col] =
                pkh(c[i][n][2] * sc, c[i][n][3] * sc);
        }
    }
}

// ---------------------------------------------------------------------------
// Tensor-core flash attention, pure fp16 operands, fixed-zero softmax ref.
// Block: 64 q-rows x 1 head, 128 threads = 4 warps.
// __launch_bounds__(128,4): 512-CTA grid fully resident -> single wave.
// B-fragments loaded via ldmatrix.x4 (conflict-free at strides 40/72 halves).
// ---------------------------------------------------------------------------
__global__ __launch_bounds__(128, 4) void attn_tc(
    const uint16_t* __restrict__ qkv, const uint32_t* __restrict__ mb,
    uint16_t* __restrict__ outh, uint16_t* __restrict__ outl)
{
    __shared__ __align__(16) uint16_t Khi[64 * 40];
    __shared__ __align__(16) uint16_t Vthi[32 * 72];

    const int tid  = threadIdx.x;
    const int w    = tid >> 5;
    const int lane = tid & 31;
    const int g    = lane >> 2;
    const int t    = lane & 3;
    const int h    = blockIdx.y;
    const int q0   = blockIdx.x << 6;
    const int rA   = q0 + w * 16 + g;
    const int rB   = rA + 8;

    // ldmatrix per-lane row addressing: quadrant layout
    const int rowadd = ((lane >> 4) & 1) * 8 + (lane & 7);
    const int coladd = ((lane >> 3) & 1) * 8;
    const uint32_t kaddr = smem_u32(Khi)  + (uint32_t)(rowadd * 40 + coladd) * 2u;
    const uint32_t vaddr = smem_u32(Vthi) + (uint32_t)(rowadd * 72 + coladd) * 2u;

    // ---- Q fragments: direct packed loads (scale already folded) ----
    uint32_t qa[2][4];
#pragma unroll
    for (int s = 0; s < 2; s++) {
        const size_t bA = (size_t)rA * 768 + h * 32 + 16 * s + 2 * t;
        const size_t bB = (size_t)rB * 768 + h * 32 + 16 * s + 2 * t;
        qa[s][0] = *(const uint32_t*)&qkv[bA];
        qa[s][1] = *(const uint32_t*)&qkv[bB];
        qa[s][2] = *(const uint32_t*)&qkv[bA + 8];
        qa[s][3] = *(const uint32_t*)&qkv[bB + 8];
    }

    float lA = 0.0f, lB = 0.0f;
    float o[4][4];
#pragma unroll
    for (int n = 0; n < 4; n++)
#pragma unroll
        for (int i = 0; i < 4; i++) o[n][i] = 0.0f;

    // K loader: thread owns key klr, 16-half chunk klc
    const int klr = tid >> 1;
    const int klc = (tid & 1) * 16;
    const uint16_t* kbg = qkv + (size_t)klr * 768 + 256 + h * 32 + klc;
    // V loader: thread owns keys {2vj, 2vj+1}, 8-half chunk vc
    const int vj = tid >> 2;
    const int vc = (tid & 3) * 8;
    const uint16_t* vbg = qkv + (size_t)(2 * vj) * 768 + 512 + h * 32 + vc;

    uint4 kr0, kr1, va, vb;
    kr0 = ((const uint4*)kbg)[0];
    kr1 = ((const uint4*)kbg)[1];
    va  = *(const uint4*)vbg;
    vb  = *(const uint4*)(vbg + 768);

    for (int T = 0; T < 64; T++) {
        __syncthreads();
        // K tile: raw copy
        *(uint4*)&Khi[klr * 40 + klc]     = kr0;
        *(uint4*)&Khi[klr * 40 + klc + 8] = kr1;
        // V^T tile: PRMT-interleave keys 2vj / 2vj+1 per dh
        {
            const uint32_t aw[4] = {va.x, va.y, va.z, va.w};
            const uint32_t bw[4] = {vb.x, vb.y, vb.z, vb.w};
#pragma unroll
            for (int d = 0; d < 8; d++) {
                uint32_t x = prmt(aw[d >> 1], bw[d >> 1],
                                  (d & 1) ? 0x7632u : 0x5410u);
                *(uint32_t*)&Vthi[(vc + d) * 72 + 2 * vj] = x;
            }
        }
        __syncthreads();

        // prefetch next tile
        if (T < 63) {
            const size_t off = (size_t)(T + 1) * 64 * 768;
            kr0 = ((const uint4*)(kbg + off))[0];
            kr1 = ((const uint4*)(kbg + off))[1];
            va  = *(const uint4*)(vbg + off);
            vb  = *(const uint4*)(vbg + off + 768);
        }

        const uint32_t wA0 = mb[(size_t)rA * 128 + 2 * T];
        const uint32_t wA1 = mb[(size_t)rA * 128 + 2 * T + 1];
        const uint32_t wB0 = mb[(size_t)rB * 128 + 2 * T];
        const uint32_t wB1 = mb[(size_t)rB * 128 + 2 * T + 1];

        // ---- S = Q.K^T : ldmatrix.x4 B-frags, 4 pairs x 2 k-steps ----
        float c[8][4];
#pragma unroll
        for (int n = 0; n < 8; n++)
#pragma unroll
            for (int i = 0; i < 4; i++) c[n][i] = 0.0f;

#pragma unroll
        for (int p = 0; p < 4; p++) {
#pragma unroll
            for (int s = 0; s < 2; s++) {
                uint32_t b[4];
                ldsm4(b, kaddr + (uint32_t)((p * 16 * 40 + s * 16) * 2));
                mma_f16(c[2 * p],     qa[s], b[0], b[1]);
                mma_f16(c[2 * p + 1], qa[s], b[2], b[3]);
            }
        }

        // ---- mask + p = 2^s + l accumulation ----
#pragma unroll
        for (int n = 0; n < 8; n++) {
            const int sh = (8 * n + 2 * t) & 31;
            uint32_t bA = ((n < 4) ? wA0 : wA1) >> sh;
            uint32_t bB = ((n < 4) ? wB0 : wB1) >> sh;
            c[n][0] = ex2((bA & 1u) ? c[n][0] : NEGBIG);
            c[n][1] = ex2((bA & 2u) ? c[n][1] : NEGBIG);
            c[n][2] = ex2((bB & 1u) ? c[n][2] : NEGBIG);
            c[n][3] = ex2((bB & 2u) ? c[n][3] : NEGBIG);
            lA += c[n][0] + c[n][1];
            lB += c[n][2] + c[n][3];
        }

        // ---- out += P.V : ldmatrix.x4 V-frags, 4 k-steps x 2 pairs ----
#pragma unroll
        for (int s = 0; s < 4; s++) {
            uint32_t ph[4];
            ph[0] = pkh(c[2 * s][0],     c[2 * s][1]);
            ph[1] = pkh(c[2 * s][2],     c[2 * s][3]);
            ph[2] = pkh(c[2 * s + 1][0], c[2 * s + 1][1]);
            ph[3] = pkh(c[2 * s + 1][2], c[2 * s + 1][3]);
#pragma unroll
            for (int p = 0; p < 2; p++) {
                uint32_t b[4];
                ldsm4(b, vaddr + (uint32_t)((p * 16 * 72 + s * 16) * 2));
                mma_f16(o[2 * p],     ph, b[0], b[1]);
                mma_f16(o[2 * p + 1], ph, b[2], b[3]);
            }
        }
    }

    // ---- reduce l across the 4 t-threads of each row, normalize, store ----
    lA += __shfl_xor_sync(0xffffffffu, lA, 1);
    lA += __shfl_xor_sync(0xffffffffu, lA, 2);
    lB += __shfl_xor_sync(0xffffffffu, lB, 1);
    lB += __shfl_xor_sync(0xffffffffu, lB, 2);
    const float invA = 1.0f / lA;
    const float invB = 1.0f / lB;
    const int cb = h * 32 + 2 * t;
#pragma unroll
    for (int n = 0; n < 4; n++) {
        uint32_t hh, ll;
        splith(o[n][0] * invA, o[n][1] * invA, hh, ll);
        *(uint32_t*)&outh[(size_t)rA * 256 + cb + 8 * n] = hh;
        *(uint32_t*)&outl[(size_t)rA * 256 + cb + 8 * n] = ll;
        splith(o[n][2] * invB, o[n][3] * invB, hh, ll);
        *(uint32_t*)&outh[(size_t)rB * 256 + cb + 8 * n] = hh;
        *(uint32_t*)&outl[(size_t)rB * 256 + cb + 8 * n] = ll;
    }
}

// ---------------------------------------------------------------------------
extern "C" void kernel_launch(void* const* d_in, const int* in_sizes, int n_in,
                              void* d_out, int out_size)
{
    const float* x      = (const float*)d_in[0];
    const int*   adj    = (const int*)d_in[1];
    const float* w_qkv  = (const float*)d_in[2];
    const float* w_proj = (const float*)d_in[3];
    const float* b_proj = (const float*)d_in[4];
    float*       out    = (float*)d_out;

    void *pm, *pxh, *pxl, *pqh, *pql, *pph, *ppl, *pkv, *pah, *pal;
    cudaGetSymbolAddress(&pm, g_mask);
    cudaGetSymbolAddress(&pxh, g_xhi);  cudaGetSymbolAddress(&pxl, g_xlo);
    cudaGetSymbolAddress(&pqh, g_wqh);  cudaGetSymbolAddress(&pql, g_wql);
    cudaGetSymbolAddress(&pph, g_wph);  cudaGetSymbolAddress(&ppl, g_wpl);
    cudaGetSymbolAddress(&pkv, g_kvh);
    cudaGetSymbolAddress(&pah, g_ath);  cudaGetSymbolAddress(&pal, g_atl);

    uint32_t* msk = (uint32_t*)pm;
    uint16_t* xhi = (uint16_t*)pxh; uint16_t* xlo = (uint16_t*)pxl;
    uint16_t* wqh = (uint16_t*)pqh; uint16_t* wql = (uint16_t*)pql;
    uint16_t* wph = (uint16_t*)pph; uint16_t* wpl = (uint16_t*)ppl;
    uint16_t* kvh = (uint16_t*)pkv;
    uint16_t* ath = (uint16_t*)pah; uint16_t* atl = (uint16_t*)pal;

    // 0) packs
    pack_mask<<<(NTOK * (NTOK / 32)) / 256, 256>>>(adj, msk);
    pack_halves<<<(NTOK * CDIM / 4) / 256, 256>>>(x, xhi, xlo);
    pack_halves<<<(3 * CDIM * CDIM / 4) / 256, 256>>>(w_qkv, wqh, wql);
    pack_halves<<<(CDIM * CDIM / 4) / 256, 256>>>(w_proj, wph, wpl);

    // 1) QKV projection -> fp16 (q columns pre-scaled)
    {
        dim3 grid(768 / 64, NTOK / 128);
        gemm_tch<<<grid, 256>>>(xhi, xlo, wqh, wql, kvh, NTOK, 3 * CDIM, CDIM);
    }
    // 2) tensor-core masked flash attention -> fp16 hi/lo output
    {
        dim3 grid(NTOK / 64, HEADS);
        attn_tc<<<grid, 128>>>(kvh, msk, ath, atl);
    }
    // 3) output projection + bias (f32 out)
    {
        dim3 grid(CDIM / 64, NTOK / 128);
        gemm_tc<<<grid, 256>>>(ath, atl, wph, wpl, b_proj, out,
                               NTOK, CDIM, CDIM);
    }
}